// round 1
// baseline (speedup 1.0000x reference)
#include <cuda_runtime.h>
#include <math.h>

// ---------------- problem constants ----------------
#define BB   8
#define TT   1024
#define DD   256
#define HH   512
#define NN   16
#define RR   8
#define LL   4
#define BT   (BB*TT)        // 8192
#define BTH  (BB*TT*HH)     // 4194304
#define BTD  (BB*TT*DD)     // 2097152

// ---------------- scratch (static device globals; no allocation) ----------------
__device__ float g_h  [BTD];
__device__ float g_ln [BTD];
__device__ float g_v  [BTH];
__device__ float g_vc [BTH];
__device__ float g_dt [BTH];
__device__ float g_dtr[BT*RR];
__device__ float g_y  [BTH];

// ---------------- helpers ----------------
__device__ __forceinline__ float block_reduce_256(float v, float* red8) {
    #pragma unroll
    for (int o = 16; o; o >>= 1) v += __shfl_xor_sync(0xffffffffu, v, o);
    if ((threadIdx.x & 31) == 0) red8[threadIdx.x >> 5] = v;
    __syncthreads();
    float s = 0.f;
    #pragma unroll
    for (int i = 0; i < 8; i++) s += red8[i];
    return s;
}

__device__ __forceinline__ float silu_f(float x) {
    return x / (1.f + __expf(-x));
}

// ---------------- embed + positional encoding ----------------
__global__ void embed_kernel(const float* __restrict__ x,
                             const float* __restrict__ emb_w,
                             const float* __restrict__ emb_b) {
    int bt = blockIdx.x;          // 0..8191
    int d  = threadIdx.x;         // 0..255
    __shared__ float sx[32];
    if (d < 32) sx[d] = x[bt * 32 + d];
    __syncthreads();
    float acc = emb_b[d];
    const float* w = emb_w + d * 32;
    #pragma unroll
    for (int i = 0; i < 32; i++) acc = fmaf(sx[i], w[i], acc);
    int t = bt & (TT - 1);
    int k2 = d & ~1;
    float div = expf((float)k2 * (-9.210340371976184f / 256.0f));
    float ang = (float)t * div;
    acc += (d & 1) ? cosf(ang) : sinf(ang);
    g_h[bt * DD + d] = acc;
}

// ---------------- layernorm over D=256 ----------------
__global__ void ln_kernel(const float* __restrict__ g,
                          const float* __restrict__ b) {
    __shared__ float red1[8], red2[8];
    int row = blockIdx.x;
    int d   = threadIdx.x;
    float v = g_h[row * DD + d];
    float mean = block_reduce_256(v, red1) * (1.f / 256.f);
    float c = v - mean;
    float var = block_reduce_256(c * c, red2) * (1.f / 256.f);
    g_ln[row * DD + d] = c * rsqrtf(var + 1e-5f) * g[d] + b[d];
}

// ---------------- NT SGEMM: C[M,N] = A[M,K] * W[N,K]^T (+C if acc) ----------------
// BM=128, BN=64, BK=16, 256 threads, 8x4 per thread
__global__ __launch_bounds__(256) void sgemm_nt(
    const float* __restrict__ A, const float* __restrict__ W,
    float* __restrict__ C, int M, int N, int K, int accumulate)
{
    __shared__ float As[16][128];
    __shared__ float Bs[16][64];
    const int tid = threadIdx.x;
    const int bm  = blockIdx.y * 128;
    const int bn  = blockIdx.x * 64;
    const int tm  = (tid >> 4) * 8;   // 0..120
    const int tn  = (tid & 15) * 4;   // 0..60
    const int lrow = tid >> 2;        // 0..63
    const int lk   = (tid & 3) * 4;   // 0,4,8,12

    float acc[8][4];
    #pragma unroll
    for (int i = 0; i < 8; i++)
        #pragma unroll
        for (int j = 0; j < 4; j++) acc[i][j] = 0.f;

    const float* Ap0 = A + (size_t)(bm + lrow) * K + lk;
    const float* Ap1 = A + (size_t)(bm + lrow + 64) * K + lk;
    const float* Wp  = W + (size_t)(bn + lrow) * K + lk;

    for (int kt = 0; kt < K; kt += 16) {
        float4 a0 = *(const float4*)(Ap0 + kt);
        float4 a1 = *(const float4*)(Ap1 + kt);
        float4 b0 = *(const float4*)(Wp  + kt);
        As[lk + 0][lrow] = a0.x; As[lk + 1][lrow] = a0.y;
        As[lk + 2][lrow] = a0.z; As[lk + 3][lrow] = a0.w;
        As[lk + 0][lrow + 64] = a1.x; As[lk + 1][lrow + 64] = a1.y;
        As[lk + 2][lrow + 64] = a1.z; As[lk + 3][lrow + 64] = a1.w;
        Bs[lk + 0][lrow] = b0.x; Bs[lk + 1][lrow] = b0.y;
        Bs[lk + 2][lrow] = b0.z; Bs[lk + 3][lrow] = b0.w;
        __syncthreads();
        #pragma unroll
        for (int k = 0; k < 16; k++) {
            float4 af0 = *(const float4*)&As[k][tm];
            float4 af1 = *(const float4*)&As[k][tm + 4];
            float4 bf  = *(const float4*)&Bs[k][tn];
            float a[8] = {af0.x, af0.y, af0.z, af0.w, af1.x, af1.y, af1.z, af1.w};
            float b[4] = {bf.x, bf.y, bf.z, bf.w};
            #pragma unroll
            for (int i = 0; i < 8; i++)
                #pragma unroll
                for (int j = 0; j < 4; j++)
                    acc[i][j] = fmaf(a[i], b[j], acc[i][j]);
        }
        __syncthreads();
    }

    #pragma unroll
    for (int i = 0; i < 8; i++) {
        float* crow = C + (size_t)(bm + tm + i) * N + bn + tn;
        #pragma unroll
        for (int j = 0; j < 4; j++) {
            float out = acc[i][j];
            if (accumulate) out += crow[j];
            crow[j] = out;
        }
    }
}

// ---------------- depthwise conv(k=3, pad=1) + silu ----------------
__global__ void conv_silu_kernel(const float* __restrict__ w) {
    int idx = blockIdx.x * blockDim.x + threadIdx.x;  // < BTH
    int h = idx & (HH - 1);
    int t = (idx >> 9) & (TT - 1);
    float w0 = w[h * 3 + 0], w1 = w[h * 3 + 1], w2 = w[h * 3 + 2];
    float acc = w1 * g_v[idx];
    if (t > 0)      acc = fmaf(w0, g_v[idx - HH], acc);
    if (t < TT - 1) acc = fmaf(w2, g_v[idx + HH], acc);
    g_vc[idx] = silu_f(acc);
}

// ---------------- dt1: (BT,H)x(R,H)^T -> relu, R=8 ----------------
__global__ void dt1_kernel(const float* __restrict__ w,
                           const float* __restrict__ bias) {
    int bt = blockIdx.x;
    int tid = threadIdx.x;          // 256
    float acc[RR];
    #pragma unroll
    for (int r = 0; r < RR; r++) acc[r] = 0.f;
    #pragma unroll
    for (int h = tid; h < HH; h += 256) {
        float xv = g_vc[bt * HH + h];
        #pragma unroll
        for (int r = 0; r < RR; r++) acc[r] = fmaf(xv, w[r * HH + h], acc[r]);
    }
    __shared__ float red[8][RR];
    #pragma unroll
    for (int r = 0; r < RR; r++) {
        float v = acc[r];
        #pragma unroll
        for (int o = 16; o; o >>= 1) v += __shfl_xor_sync(0xffffffffu, v, o);
        if ((tid & 31) == 0) red[tid >> 5][r] = v;
    }
    __syncthreads();
    if (tid < RR) {
        float s = 0.f;
        #pragma unroll
        for (int wp = 0; wp < 8; wp++) s += red[wp][tid];
        s += bias[tid];
        g_dtr[bt * RR + tid] = fmaxf(s, 0.f);
    }
}

// ---------------- dt2 + softplus ----------------
__global__ void dt2_softplus_kernel(const float* __restrict__ w,
                                    const float* __restrict__ bias) {
    int idx = blockIdx.x * blockDim.x + threadIdx.x;  // < BTH
    int h  = idx & (HH - 1);
    int bt = idx >> 9;
    float acc = bias[h];
    const float* dr = g_dtr + bt * RR;
    const float* wh = w + h * RR;
    #pragma unroll
    for (int r = 0; r < RR; r++) acc = fmaf(dr[r], wh[r], acc);
    g_dt[idx] = (acc > 15.f) ? acc : log1pf(__expf(acc));
}

// ---------------- selective scan ----------------
// one thread per (b,h,n); 16 lanes per channel; 128 threads = 8 channels/block
__global__ __launch_bounds__(128) void scan_kernel(const float* __restrict__ A_p,
                                                   const float* __restrict__ D_p) {
    int ch = blockIdx.x * 8 + (threadIdx.x >> 4);   // 0..4095
    int n  = threadIdx.x & 15;
    int b  = ch >> 9;
    int h  = ch & (HH - 1);
    float Ap = A_p[h * NN + n];
    float A  = -__expf(Ap);
    float invA = (fabsf(A) < 1e-5f) ? 1.f : (1.f / A);
    float Dp = D_p[h];
    const float* xptr = g_vc + (size_t)b * TT * HH + h;
    const float* dptr = g_dt + (size_t)b * TT * HH + h;
    float*       yptr = g_y  + (size_t)b * TT * HH + h;
    float state = 0.f;
    #pragma unroll 4
    for (int t = 0; t < TT; t++) {
        float dtv = dptr[(size_t)t * HH];
        float x   = xptr[(size_t)t * HH];
        float discA = __expf(A * dtv);
        float discB = (discA - 1.f) * invA * dtv;
        state = fmaf(discA, state, discB * x);
        float part = state * Ap;
        part += __shfl_xor_sync(0xffffffffu, part, 8);
        part += __shfl_xor_sync(0xffffffffu, part, 4);
        part += __shfl_xor_sync(0xffffffffu, part, 2);
        part += __shfl_xor_sync(0xffffffffu, part, 1);
        if (n == 0) yptr[(size_t)t * HH] = fmaf(Dp, x, part);
    }
}

// ---------------- final LN (last token) + head1(silu) + head2 ----------------
__global__ void final_kernel(const float* __restrict__ fg,
                             const float* __restrict__ fb,
                             const float* __restrict__ w1,
                             const float* __restrict__ b1,
                             const float* __restrict__ w2,
                             const float* __restrict__ b2,
                             float* __restrict__ out) {
    int b = blockIdx.x;            // 0..7
    int tid = threadIdx.x;         // 256
    __shared__ float red1[8], red2[8];
    __shared__ float s_ln[DD];
    __shared__ float s_h1[DD];
    const float* row = g_h + (size_t)(b * TT + (TT - 1)) * DD;
    float v = row[tid];
    float mean = block_reduce_256(v, red1) * (1.f / 256.f);
    float c = v - mean;
    float var = block_reduce_256(c * c, red2) * (1.f / 256.f);
    s_ln[tid] = c * rsqrtf(var + 1e-5f) * fg[tid] + fb[tid];
    __syncthreads();
    float acc = b1[tid];
    const float* w1r = w1 + tid * DD;
    #pragma unroll 8
    for (int k = 0; k < DD; k++) acc = fmaf(s_ln[k], w1r[k], acc);
    s_h1[tid] = silu_f(acc);
    __syncthreads();
    if (tid < 96) {
        float a2 = b2[tid];
        const float* w2r = w2 + tid * DD;
        #pragma unroll 8
        for (int k = 0; k < DD; k++) a2 = fmaf(s_h1[k], w2r[k], a2);
        out[b * 96 + tid] = a2;
    }
}

// ---------------- launcher ----------------
extern "C" void kernel_launch(void* const* d_in, const int* in_sizes, int n_in,
                              void* d_out, int out_size) {
    const float* x      = (const float*)d_in[0];
    const float* emb_w  = (const float*)d_in[1];
    const float* emb_b  = (const float*)d_in[2];
    const float* norm_g = (const float*)d_in[3];
    const float* norm_b = (const float*)d_in[4];
    const float* in_w   = (const float*)d_in[5];
    const float* conv_w = (const float*)d_in[6];
    const float* A_p    = (const float*)d_in[7];
    const float* D_p    = (const float*)d_in[8];
    const float* dt1_w  = (const float*)d_in[9];
    const float* dt1_b  = (const float*)d_in[10];
    const float* dt2_w  = (const float*)d_in[11];
    const float* dt2_b  = (const float*)d_in[12];
    const float* out_w  = (const float*)d_in[13];
    const float* fin_g  = (const float*)d_in[14];
    const float* fin_b  = (const float*)d_in[15];
    const float* h1_w   = (const float*)d_in[16];
    const float* h1_b   = (const float*)d_in[17];
    const float* h2_w   = (const float*)d_in[18];
    const float* h2_b   = (const float*)d_in[19];
    float* out = (float*)d_out;

    float *ph, *pln, *pv, *pvc, *pdt, *py;
    cudaGetSymbolAddress((void**)&ph,  g_h);
    cudaGetSymbolAddress((void**)&pln, g_ln);
    cudaGetSymbolAddress((void**)&pv,  g_v);
    cudaGetSymbolAddress((void**)&pvc, g_vc);
    cudaGetSymbolAddress((void**)&pdt, g_dt);
    cudaGetSymbolAddress((void**)&py,  g_y);

    embed_kernel<<<BT, 256>>>(x, emb_w, emb_b);

    for (int l = 0; l < LL; l++) {
        ln_kernel<<<BT, 256>>>(norm_g + l * DD, norm_b + l * DD);

        // v = ln @ in_w[l]^T   (M=8192, N=512, K=256)
        sgemm_nt<<<dim3(HH / 64, BT / 128), 256>>>(
            pln, in_w + (size_t)l * HH * DD, pv, BT, HH, DD, 0);

        conv_silu_kernel<<<BTH / 256, 256>>>(conv_w + (size_t)l * HH * 3);

        dt1_kernel<<<BT, 256>>>(dt1_w + (size_t)l * RR * HH, dt1_b + l * RR);
        dt2_softplus_kernel<<<BTH / 256, 256>>>(dt2_w + (size_t)l * HH * RR,
                                                dt2_b + l * HH);

        scan_kernel<<<(BB * HH) / 8, 128>>>(A_p + (size_t)l * HH * NN,
                                            D_p + l * HH);

        // h += y @ out_w[l]^T  (M=8192, N=256, K=512)
        sgemm_nt<<<dim3(DD / 64, BT / 128), 256>>>(
            py, out_w + (size_t)l * DD * HH, ph, BT, DD, HH, 1);
    }

    final_kernel<<<BB, 256>>>(fin_g, fin_b, h1_w, h1_b, h2_w, h2_b, out);
}

// round 3
// speedup vs baseline: 1.1179x; 1.1179x over previous
#include <cuda_runtime.h>
#include <cuda_bf16.h>
#include <cstdint>
#include <math.h>

// ---------------- problem constants ----------------
#define BB   8
#define TT   1024
#define DD   256
#define HH   512
#define NN   16
#define RR   8
#define LL   4
#define BT   (BB*TT)        // 8192
#define BTH  (BB*TT*HH)     // 4194304
#define BTD  (BB*TT*DD)     // 2097152
#define NW   (LL*HH*DD)     // 524288 (per weight tensor)

// ---------------- scratch (static device globals; no allocation) ----------------
__device__ float g_h  [BTD];
__device__ float g_v  [BTH];
__device__ float g_vc [BTH];
__device__ float g_dt [BTH];
__device__ float g_dtr[BT*RR];
__device__ __nv_bfloat16 g_lnh[BTD], g_lnl[BTD];
__device__ __nv_bfloat16 g_yh [BTH], g_yl [BTH];
__device__ __nv_bfloat16 g_iwh[NW],  g_iwl[NW];
__device__ __nv_bfloat16 g_owh[NW],  g_owl[NW];

// ---------------- helpers ----------------
__device__ __forceinline__ float block_reduce_256(float v, float* red8) {
    #pragma unroll
    for (int o = 16; o; o >>= 1) v += __shfl_xor_sync(0xffffffffu, v, o);
    if ((threadIdx.x & 31) == 0) red8[threadIdx.x >> 5] = v;
    __syncthreads();
    float s = 0.f;
    #pragma unroll
    for (int i = 0; i < 8; i++) s += red8[i];
    return s;
}

__device__ __forceinline__ float silu_f(float x) {
    return x / (1.f + __expf(-x));
}

__device__ __forceinline__ void split_bf16(float v, __nv_bfloat16& h, __nv_bfloat16& l) {
    h = __float2bfloat16(v);
    l = __float2bfloat16(v - __bfloat162float(h));
}

__device__ __forceinline__ void ldsm4(unsigned int r[4], const void* p) {
    unsigned int a = (unsigned int)__cvta_generic_to_shared(p);
    asm volatile("ldmatrix.sync.aligned.m8n8.x4.shared.b16 {%0,%1,%2,%3}, [%4];"
                 : "=r"(r[0]), "=r"(r[1]), "=r"(r[2]), "=r"(r[3]) : "r"(a));
}

__device__ __forceinline__ void mma_bf16(float c[4], const unsigned int a[4],
                                         unsigned int b0, unsigned int b1) {
    asm volatile(
        "mma.sync.aligned.m16n8k16.row.col.f32.bf16.bf16.f32 "
        "{%0,%1,%2,%3},{%4,%5,%6,%7},{%8,%9},{%0,%1,%2,%3};"
        : "+f"(c[0]), "+f"(c[1]), "+f"(c[2]), "+f"(c[3])
        : "r"(a[0]), "r"(a[1]), "r"(a[2]), "r"(a[3]), "r"(b0), "r"(b1));
}

// ---------------- embed + positional encoding ----------------
__global__ void embed_kernel(const float* __restrict__ x,
                             const float* __restrict__ emb_w,
                             const float* __restrict__ emb_b) {
    int bt = blockIdx.x;
    int d  = threadIdx.x;
    __shared__ float sx[32];
    if (d < 32) sx[d] = x[bt * 32 + d];
    __syncthreads();
    float acc = emb_b[d];
    const float* w = emb_w + d * 32;
    #pragma unroll
    for (int i = 0; i < 32; i++) acc = fmaf(sx[i], w[i], acc);
    int t = bt & (TT - 1);
    int k2 = d & ~1;
    float div = expf((float)k2 * (-9.210340371976184f / 256.0f));
    float ang = (float)t * div;
    acc += (d & 1) ? cosf(ang) : sinf(ang);
    g_h[bt * DD + d] = acc;
}

// ---------------- weight split: fp32 -> bf16 hi/lo ----------------
__global__ void split_weights(const float* __restrict__ in_w,
                              const float* __restrict__ out_w) {
    int i = blockIdx.x * 256 + threadIdx.x;
    if (i < NW) {
        split_bf16(in_w[i], g_iwh[i], g_iwl[i]);
    } else {
        int j = i - NW;
        split_bf16(out_w[j], g_owh[j], g_owl[j]);
    }
}

// ---------------- layernorm over D=256 -> bf16 hi/lo ----------------
__global__ void ln_kernel(const float* __restrict__ g,
                          const float* __restrict__ b) {
    __shared__ float red1[8], red2[8];
    int row = blockIdx.x;
    int d   = threadIdx.x;
    float v = g_h[row * DD + d];
    float mean = block_reduce_256(v, red1) * (1.f / 256.f);
    float c = v - mean;
    float var = block_reduce_256(c * c, red2) * (1.f / 256.f);
    float o = c * rsqrtf(var + 1e-5f) * g[d] + b[d];
    split_bf16(o, g_lnh[row * DD + d], g_lnl[row * DD + d]);
}

// ---------------- bf16x3 tensor-core GEMM ----------------
// C[M,N] (+)= A[M,K] * W[N,K]^T, A/W given as bf16 (hi,lo) pairs.
// BM=128, BN=64, BK=32, 256 threads, warp grid 4(M) x 2(N), warp tile 32x32.
#define PADK 40
__global__ __launch_bounds__(256) void gemm_bf16x3(
    const __nv_bfloat16* __restrict__ Ah, const __nv_bfloat16* __restrict__ Al,
    const __nv_bfloat16* __restrict__ Wh, const __nv_bfloat16* __restrict__ Wl,
    float* __restrict__ C, int M, int N, int K, int accumulate)
{
    __shared__ __nv_bfloat16 sAh[128][PADK], sAl[128][PADK];
    __shared__ __nv_bfloat16 sWh[64][PADK],  sWl[64][PADK];

    const int tid  = threadIdx.x;
    const int lane = tid & 31;
    const int wid  = tid >> 5;
    const int wm   = (wid & 3) * 32;
    const int wn   = (wid >> 2) * 32;
    const int bm   = blockIdx.y * 128;
    const int bn   = blockIdx.x * 64;

    float acc[2][4][4];
    #pragma unroll
    for (int a = 0; a < 2; a++)
        #pragma unroll
        for (int b = 0; b < 4; b++)
            #pragma unroll
            for (int c = 0; c < 4; c++) acc[a][b][c] = 0.f;

    const int lrow = tid >> 2;          // 0..63
    const int lcol = (tid & 3) * 8;     // 0,8,16,24

    // ldmatrix addressing
    const int a_row = lane & 15;
    const int a_col = (lane >> 4) << 3;
    const int bq    = lane >> 3;
    const int b_row = (lane & 7) + ((bq >> 1) << 3);
    const int b_col = (bq & 1) << 3;

    for (int kt = 0; kt < K; kt += 32) {
        const __nv_bfloat16* pA = Ah + (size_t)(bm + lrow) * K + kt + lcol;
        const __nv_bfloat16* pa = Al + (size_t)(bm + lrow) * K + kt + lcol;
        *(uint4*)&sAh[lrow     ][lcol] = *(const uint4*)pA;
        *(uint4*)&sAh[lrow + 64][lcol] = *(const uint4*)(pA + (size_t)64 * K);
        *(uint4*)&sAl[lrow     ][lcol] = *(const uint4*)pa;
        *(uint4*)&sAl[lrow + 64][lcol] = *(const uint4*)(pa + (size_t)64 * K);
        const __nv_bfloat16* pW = Wh + (size_t)(bn + lrow) * K + kt + lcol;
        const __nv_bfloat16* pw = Wl + (size_t)(bn + lrow) * K + kt + lcol;
        *(uint4*)&sWh[lrow][lcol] = *(const uint4*)pW;
        *(uint4*)&sWl[lrow][lcol] = *(const uint4*)pw;
        __syncthreads();

        #pragma unroll
        for (int ks = 0; ks < 2; ks++) {
            const int k0 = ks * 16;
            unsigned int ah[2][4], al[2][4];
            #pragma unroll
            for (int mt = 0; mt < 2; mt++) {
                ldsm4(ah[mt], &sAh[wm + mt * 16 + a_row][k0 + a_col]);
                ldsm4(al[mt], &sAl[wm + mt * 16 + a_row][k0 + a_col]);
            }
            unsigned int bh[2][4], bl[2][4];
            #pragma unroll
            for (int nb = 0; nb < 2; nb++) {
                ldsm4(bh[nb], &sWh[wn + nb * 16 + b_row][k0 + b_col]);
                ldsm4(bl[nb], &sWl[wn + nb * 16 + b_row][k0 + b_col]);
            }
            #pragma unroll
            for (int mt = 0; mt < 2; mt++) {
                #pragma unroll
                for (int nt = 0; nt < 4; nt++) {
                    const int nb = nt >> 1, hf = (nt & 1) * 2;
                    mma_bf16(acc[mt][nt], ah[mt], bh[nb][hf], bh[nb][hf + 1]);
                    mma_bf16(acc[mt][nt], ah[mt], bl[nb][hf], bl[nb][hf + 1]);
                    mma_bf16(acc[mt][nt], al[mt], bh[nb][hf], bh[nb][hf + 1]);
                }
            }
        }
        __syncthreads();
    }

    const int cg = lane >> 2;
    const int ct = (lane & 3) * 2;
    #pragma unroll
    for (int mt = 0; mt < 2; mt++) {
        #pragma unroll
        for (int nt = 0; nt < 4; nt++) {
            int r0 = bm + wm + mt * 16 + cg;
            int c0 = bn + wn + nt * 8 + ct;
            float2* p0 = (float2*)(C + (size_t)r0 * N + c0);
            float2* p1 = (float2*)(C + (size_t)(r0 + 8) * N + c0);
            float2 v0 = make_float2(acc[mt][nt][0], acc[mt][nt][1]);
            float2 v1 = make_float2(acc[mt][nt][2], acc[mt][nt][3]);
            if (accumulate) {
                float2 o0 = *p0, o1 = *p1;
                v0.x += o0.x; v0.y += o0.y;
                v1.x += o1.x; v1.y += o1.y;
            }
            *p0 = v0; *p1 = v1;
        }
    }
}

// ---------------- depthwise conv(k=3, pad=1) + silu, float4 ----------------
__global__ void conv_silu_kernel(const float* __restrict__ w) {
    int i4 = blockIdx.x * blockDim.x + threadIdx.x;   // < BTH/4
    int idx = i4 * 4;
    int h = idx & (HH - 1);
    int t = (idx >> 9) & (TT - 1);
    float4 v0 = *(const float4*)(g_v + idx);
    float4 vm = make_float4(0.f, 0.f, 0.f, 0.f);
    float4 vp = make_float4(0.f, 0.f, 0.f, 0.f);
    if (t > 0)      vm = *(const float4*)(g_v + idx - HH);
    if (t < TT - 1) vp = *(const float4*)(g_v + idx + HH);
    float4 r;
    #pragma unroll
    for (int j = 0; j < 4; j++) {
        const float* wj = w + (h + j) * 3;
        float a = ((const float*)&v0)[j] * wj[1];
        a = fmaf(((const float*)&vm)[j], wj[0], a);
        a = fmaf(((const float*)&vp)[j], wj[2], a);
        ((float*)&r)[j] = silu_f(a);
    }
    *(float4*)(g_vc + idx) = r;
}

// ---------------- dt1: (BT,H)x(R,H)^T -> relu, R=8 ----------------
__global__ void dt1_kernel(const float* __restrict__ w,
                           const float* __restrict__ bias) {
    int bt = blockIdx.x;
    int tid = threadIdx.x;          // 256
    float acc[RR];
    #pragma unroll
    for (int r = 0; r < RR; r++) acc[r] = 0.f;
    #pragma unroll
    for (int h = tid; h < HH; h += 256) {
        float xv = g_vc[bt * HH + h];
        #pragma unroll
        for (int r = 0; r < RR; r++) acc[r] = fmaf(xv, w[r * HH + h], acc[r]);
    }
    __shared__ float red[8][RR];
    #pragma unroll
    for (int r = 0; r < RR; r++) {
        float v = acc[r];
        #pragma unroll
        for (int o = 16; o; o >>= 1) v += __shfl_xor_sync(0xffffffffu, v, o);
        if ((tid & 31) == 0) red[tid >> 5][r] = v;
    }
    __syncthreads();
    if (tid < RR) {
        float s = 0.f;
        #pragma unroll
        for (int wp = 0; wp < 8; wp++) s += red[wp][tid];
        s += bias[tid];
        g_dtr[bt * RR + tid] = fmaxf(s, 0.f);
    }
}

// ---------------- dt2 + softplus ----------------
__global__ void dt2_softplus_kernel(const float* __restrict__ w,
                                    const float* __restrict__ bias) {
    int idx = blockIdx.x * blockDim.x + threadIdx.x;  // < BTH
    int h  = idx & (HH - 1);
    int bt = idx >> 9;
    float acc = bias[h];
    const float* dr = g_dtr + bt * RR;
    const float* wh = w + h * RR;
    #pragma unroll
    for (int r = 0; r < RR; r++) acc = fmaf(dr[r], wh[r], acc);
    g_dt[idx] = (acc > 15.f) ? acc : log1pf(__expf(acc));
}

// ---------------- selective scan -> y as bf16 hi/lo ----------------
__global__ __launch_bounds__(128) void scan_kernel(const float* __restrict__ A_p,
                                                   const float* __restrict__ D_p) {
    int ch = blockIdx.x * 8 + (threadIdx.x >> 4);   // 0..4095
    int n  = threadIdx.x & 15;
    int b  = ch >> 9;
    int h  = ch & (HH - 1);
    float Ap = A_p[h * NN + n];
    float A  = -__expf(Ap);
    float invA = (fabsf(A) < 1e-5f) ? 1.f : (1.f / A);
    float Dp = D_p[h];
    const float* xptr = g_vc + (size_t)b * TT * HH + h;
    const float* dptr = g_dt + (size_t)b * TT * HH + h;
    __nv_bfloat16* yh = g_yh + (size_t)b * TT * HH + h;
    __nv_bfloat16* yl = g_yl + (size_t)b * TT * HH + h;
    float state = 0.f;
    #pragma unroll 4
    for (int t = 0; t < TT; t++) {
        float dtv = dptr[(size_t)t * HH];
        float x   = xptr[(size_t)t * HH];
        float discA = __expf(A * dtv);
        float discB = (discA - 1.f) * invA * dtv;
        state = fmaf(discA, state, discB * x);
        float part = state * Ap;
        part += __shfl_xor_sync(0xffffffffu, part, 8);
        part += __shfl_xor_sync(0xffffffffu, part, 4);
        part += __shfl_xor_sync(0xffffffffu, part, 2);
        part += __shfl_xor_sync(0xffffffffu, part, 1);
        if (n == 0) {
            float y = fmaf(Dp, x, part);
            __nv_bfloat16 hh, ll;
            split_bf16(y, hh, ll);
            yh[(size_t)t * HH] = hh;
            yl[(size_t)t * HH] = ll;
        }
    }
}

// ---------------- final LN (last token) + head1(silu) + head2 ----------------
__global__ void final_kernel(const float* __restrict__ fg,
                             const float* __restrict__ fb,
                             const float* __restrict__ w1,
                             const float* __restrict__ b1,
                             const float* __restrict__ w2,
                             const float* __restrict__ b2,
                             float* __restrict__ out) {
    int b = blockIdx.x;            // 0..7
    int tid = threadIdx.x;         // 256
    __shared__ float red1[8], red2[8];
    __shared__ float s_ln[DD];
    __shared__ float s_h1[DD];
    const float* row = g_h + (size_t)(b * TT + (TT - 1)) * DD;
    float v = row[tid];
    float mean = block_reduce_256(v, red1) * (1.f / 256.f);
    float c = v - mean;
    float var = block_reduce_256(c * c, red2) * (1.f / 256.f);
    s_ln[tid] = c * rsqrtf(var + 1e-5f) * fg[tid] + fb[tid];
    __syncthreads();
    float acc = b1[tid];
    const float* w1r = w1 + tid * DD;
    #pragma unroll 8
    for (int k = 0; k < DD; k++) acc = fmaf(s_ln[k], w1r[k], acc);
    s_h1[tid] = silu_f(acc);
    __syncthreads();
    if (tid < 96) {
        float a2 = b2[tid];
        const float* w2r = w2 + tid * DD;
        #pragma unroll 8
        for (int k = 0; k < DD; k++) a2 = fmaf(s_h1[k], w2r[k], a2);
        out[b * 96 + tid] = a2;
    }
}

// ---------------- launcher ----------------
extern "C" void kernel_launch(void* const* d_in, const int* in_sizes, int n_in,
                              void* d_out, int out_size) {
    const float* x      = (const float*)d_in[0];
    const float* emb_w  = (const float*)d_in[1];
    const float* emb_b  = (const float*)d_in[2];
    const float* norm_g = (const float*)d_in[3];
    const float* norm_b = (const float*)d_in[4];
    const float* in_w   = (const float*)d_in[5];
    const float* conv_w = (const float*)d_in[6];
    const float* A_p    = (const float*)d_in[7];
    const float* D_p    = (const float*)d_in[8];
    const float* dt1_w  = (const float*)d_in[9];
    const float* dt1_b  = (const float*)d_in[10];
    const float* dt2_w  = (const float*)d_in[11];
    const float* dt2_b  = (const float*)d_in[12];
    const float* out_w  = (const float*)d_in[13];
    const float* fin_g  = (const float*)d_in[14];
    const float* fin_b  = (const float*)d_in[15];
    const float* h1_w   = (const float*)d_in[16];
    const float* h1_b   = (const float*)d_in[17];
    const float* h2_w   = (const float*)d_in[18];
    const float* h2_b   = (const float*)d_in[19];
    float* out = (float*)d_out;

    float *ph, *pv;
    cudaGetSymbolAddress((void**)&ph,  g_h);
    cudaGetSymbolAddress((void**)&pv,  g_v);
    __nv_bfloat16 *plnh, *plnl, *pyh, *pyl, *piwh, *piwl, *powh, *powl;
    cudaGetSymbolAddress((void**)&plnh, g_lnh);
    cudaGetSymbolAddress((void**)&plnl, g_lnl);
    cudaGetSymbolAddress((void**)&pyh,  g_yh);
    cudaGetSymbolAddress((void**)&pyl,  g_yl);
    cudaGetSymbolAddress((void**)&piwh, g_iwh);
    cudaGetSymbolAddress((void**)&piwl, g_iwl);
    cudaGetSymbolAddress((void**)&powh, g_owh);
    cudaGetSymbolAddress((void**)&powl, g_owl);

    embed_kernel<<<BT, 256>>>(x, emb_w, emb_b);
    split_weights<<<(2 * NW) / 256, 256>>>(in_w, out_w);

    for (int l = 0; l < LL; l++) {
        ln_kernel<<<BT, 256>>>(norm_g + l * DD, norm_b + l * DD);

        // v = ln @ in_w[l]^T   (M=8192, N=512, K=256)
        gemm_bf16x3<<<dim3(HH / 64, BT / 128), 256>>>(
            plnh, plnl,
            piwh + (size_t)l * HH * DD, piwl + (size_t)l * HH * DD,
            pv, BT, HH, DD, 0);

        conv_silu_kernel<<<BTH / 1024, 256>>>(conv_w + (size_t)l * HH * 3);

        dt1_kernel<<<BT, 256>>>(dt1_w + (size_t)l * RR * HH, dt1_b + l * RR);
        dt2_softplus_kernel<<<BTH / 256, 256>>>(dt2_w + (size_t)l * HH * RR,
                                                dt2_b + l * HH);

        scan_kernel<<<(BB * HH) / 8, 128>>>(A_p + (size_t)l * HH * NN,
                                            D_p + l * HH);

        // h += y @ out_w[l]^T  (M=8192, N=256, K=512)
        gemm_bf16x3<<<dim3(DD / 64, BT / 128), 256>>>(
            pyh, pyl,
            powh + (size_t)l * DD * HH, powl + (size_t)l * DD * HH,
            ph, BT, DD, HH, 1);
    }

    final_kernel<<<BB, 256>>>(fin_g, fin_b, h1_w, h1_b, h2_w, h2_b, out);
}

// round 4
// speedup vs baseline: 1.2974x; 1.1605x over previous
#include <cuda_runtime.h>
#include <cuda_bf16.h>
#include <cstdint>
#include <math.h>

// ---------------- problem constants ----------------
#define BB   8
#define TT   1024
#define DD   256
#define HH   512
#define NN   16
#define RR   8
#define LL   4
#define BT   (BB*TT)        // 8192
#define BTH  (BB*TT*HH)     // 4194304
#define BTD  (BB*TT*DD)     // 2097152
#define NW   (LL*HH*DD)     // 524288 (per weight tensor)

// ---------------- scratch (static device globals; no allocation) ----------------
__device__ float g_h  [BTD];
__device__ float g_v  [BTH];        // [bt][h]  (gemm1 output)
__device__ float g_vcT[BTH];        // [h][bt]  (conv+silu, transposed)
__device__ float g_dtT[BTH];        // [h][bt]  (softplus dt, transposed)
__device__ float g_dtr[BT*RR];
__device__ __nv_bfloat16 g_lnh[BTD], g_lnl[BTD];
__device__ __nv_bfloat16 g_yh [BTH], g_yl [BTH];   // [bt][h]
__device__ __nv_bfloat16 g_iwh[NW],  g_iwl[NW];
__device__ __nv_bfloat16 g_owh[NW],  g_owl[NW];

// ---------------- helpers ----------------
__device__ __forceinline__ float block_reduce_256(float v, float* red8) {
    #pragma unroll
    for (int o = 16; o; o >>= 1) v += __shfl_xor_sync(0xffffffffu, v, o);
    if ((threadIdx.x & 31) == 0) red8[threadIdx.x >> 5] = v;
    __syncthreads();
    float s = 0.f;
    #pragma unroll
    for (int i = 0; i < 8; i++) s += red8[i];
    return s;
}

__device__ __forceinline__ float silu_f(float x) {
    return x / (1.f + __expf(-x));
}

__device__ __forceinline__ void split_bf16(float v, __nv_bfloat16& h, __nv_bfloat16& l) {
    h = __float2bfloat16(v);
    l = __float2bfloat16(v - __bfloat162float(h));
}

__device__ __forceinline__ void ldsm4(unsigned int r[4], const void* p) {
    unsigned int a = (unsigned int)__cvta_generic_to_shared(p);
    asm volatile("ldmatrix.sync.aligned.m8n8.x4.shared.b16 {%0,%1,%2,%3}, [%4];"
                 : "=r"(r[0]), "=r"(r[1]), "=r"(r[2]), "=r"(r[3]) : "r"(a));
}

__device__ __forceinline__ void mma_bf16(float c[4], const unsigned int a[4],
                                         unsigned int b0, unsigned int b1) {
    asm volatile(
        "mma.sync.aligned.m16n8k16.row.col.f32.bf16.bf16.f32 "
        "{%0,%1,%2,%3},{%4,%5,%6,%7},{%8,%9},{%0,%1,%2,%3};"
        : "+f"(c[0]), "+f"(c[1]), "+f"(c[2]), "+f"(c[3])
        : "r"(a[0]), "r"(a[1]), "r"(a[2]), "r"(a[3]), "r"(b0), "r"(b1));
}

// ---------------- embed + positional encoding ----------------
__global__ void embed_kernel(const float* __restrict__ x,
                             const float* __restrict__ emb_w,
                             const float* __restrict__ emb_b) {
    int bt = blockIdx.x;
    int d  = threadIdx.x;
    __shared__ float sx[32];
    if (d < 32) sx[d] = x[bt * 32 + d];
    __syncthreads();
    float acc = emb_b[d];
    const float* w = emb_w + d * 32;
    #pragma unroll
    for (int i = 0; i < 32; i++) acc = fmaf(sx[i], w[i], acc);
    int t = bt & (TT - 1);
    int k2 = d & ~1;
    float div = expf((float)k2 * (-9.210340371976184f / 256.0f));
    float ang = (float)t * div;
    acc += (d & 1) ? cosf(ang) : sinf(ang);
    g_h[bt * DD + d] = acc;
}

// ---------------- weight split: fp32 -> bf16 hi/lo ----------------
__global__ void split_weights(const float* __restrict__ in_w,
                              const float* __restrict__ out_w) {
    int i = blockIdx.x * 256 + threadIdx.x;
    if (i < NW) {
        split_bf16(in_w[i], g_iwh[i], g_iwl[i]);
    } else {
        int j = i - NW;
        split_bf16(out_w[j], g_owh[j], g_owl[j]);
    }
}

// ---------------- layernorm over D=256 -> bf16 hi/lo ----------------
__global__ void ln_kernel(const float* __restrict__ g,
                          const float* __restrict__ b) {
    __shared__ float red1[8], red2[8];
    int row = blockIdx.x;
    int d   = threadIdx.x;
    float v = g_h[row * DD + d];
    float mean = block_reduce_256(v, red1) * (1.f / 256.f);
    float c = v - mean;
    float var = block_reduce_256(c * c, red2) * (1.f / 256.f);
    float o = c * rsqrtf(var + 1e-5f) * g[d] + b[d];
    split_bf16(o, g_lnh[row * DD + d], g_lnl[row * DD + d]);
}

// ---------------- bf16x3 tensor-core GEMM ----------------
// C[M,N] (+)= A[M,K] * W[N,K]^T, A/W given as bf16 (hi,lo) pairs.
#define PADK 40
__global__ __launch_bounds__(256) void gemm_bf16x3(
    const __nv_bfloat16* __restrict__ Ah, const __nv_bfloat16* __restrict__ Al,
    const __nv_bfloat16* __restrict__ Wh, const __nv_bfloat16* __restrict__ Wl,
    float* __restrict__ C, int M, int N, int K, int accumulate)
{
    __shared__ __nv_bfloat16 sAh[128][PADK], sAl[128][PADK];
    __shared__ __nv_bfloat16 sWh[64][PADK],  sWl[64][PADK];

    const int tid  = threadIdx.x;
    const int lane = tid & 31;
    const int wid  = tid >> 5;
    const int wm   = (wid & 3) * 32;
    const int wn   = (wid >> 2) * 32;
    const int bm   = blockIdx.y * 128;
    const int bn   = blockIdx.x * 64;

    float acc[2][4][4];
    #pragma unroll
    for (int a = 0; a < 2; a++)
        #pragma unroll
        for (int b = 0; b < 4; b++)
            #pragma unroll
            for (int c = 0; c < 4; c++) acc[a][b][c] = 0.f;

    const int lrow = tid >> 2;
    const int lcol = (tid & 3) * 8;

    const int a_row = lane & 15;
    const int a_col = (lane >> 4) << 3;
    const int bq    = lane >> 3;
    const int b_row = (lane & 7) + ((bq >> 1) << 3);
    const int b_col = (bq & 1) << 3;

    for (int kt = 0; kt < K; kt += 32) {
        const __nv_bfloat16* pA = Ah + (size_t)(bm + lrow) * K + kt + lcol;
        const __nv_bfloat16* pa = Al + (size_t)(bm + lrow) * K + kt + lcol;
        *(uint4*)&sAh[lrow     ][lcol] = *(const uint4*)pA;
        *(uint4*)&sAh[lrow + 64][lcol] = *(const uint4*)(pA + (size_t)64 * K);
        *(uint4*)&sAl[lrow     ][lcol] = *(const uint4*)pa;
        *(uint4*)&sAl[lrow + 64][lcol] = *(const uint4*)(pa + (size_t)64 * K);
        const __nv_bfloat16* pW = Wh + (size_t)(bn + lrow) * K + kt + lcol;
        const __nv_bfloat16* pw = Wl + (size_t)(bn + lrow) * K + kt + lcol;
        *(uint4*)&sWh[lrow][lcol] = *(const uint4*)pW;
        *(uint4*)&sWl[lrow][lcol] = *(const uint4*)pw;
        __syncthreads();

        #pragma unroll
        for (int ks = 0; ks < 2; ks++) {
            const int k0 = ks * 16;
            unsigned int ah[2][4], al[2][4];
            #pragma unroll
            for (int mt = 0; mt < 2; mt++) {
                ldsm4(ah[mt], &sAh[wm + mt * 16 + a_row][k0 + a_col]);
                ldsm4(al[mt], &sAl[wm + mt * 16 + a_row][k0 + a_col]);
            }
            unsigned int bh[2][4], bl[2][4];
            #pragma unroll
            for (int nb = 0; nb < 2; nb++) {
                ldsm4(bh[nb], &sWh[wn + nb * 16 + b_row][k0 + b_col]);
                ldsm4(bl[nb], &sWl[wn + nb * 16 + b_row][k0 + b_col]);
            }
            #pragma unroll
            for (int mt = 0; mt < 2; mt++) {
                #pragma unroll
                for (int nt = 0; nt < 4; nt++) {
                    const int nb = nt >> 1, hf = (nt & 1) * 2;
                    mma_bf16(acc[mt][nt], ah[mt], bh[nb][hf], bh[nb][hf + 1]);
                    mma_bf16(acc[mt][nt], ah[mt], bl[nb][hf], bl[nb][hf + 1]);
                    mma_bf16(acc[mt][nt], al[mt], bh[nb][hf], bh[nb][hf + 1]);
                }
            }
        }
        __syncthreads();
    }

    const int cg = lane >> 2;
    const int ct = (lane & 3) * 2;
    #pragma unroll
    for (int mt = 0; mt < 2; mt++) {
        #pragma unroll
        for (int nt = 0; nt < 4; nt++) {
            int r0 = bm + wm + mt * 16 + cg;
            int c0 = bn + wn + nt * 8 + ct;
            float2* p0 = (float2*)(C + (size_t)r0 * N + c0);
            float2* p1 = (float2*)(C + (size_t)(r0 + 8) * N + c0);
            float2 v0 = make_float2(acc[mt][nt][0], acc[mt][nt][1]);
            float2 v1 = make_float2(acc[mt][nt][2], acc[mt][nt][3]);
            if (accumulate) {
                float2 o0 = *p0, o1 = *p1;
                v0.x += o0.x; v0.y += o0.y;
                v1.x += o1.x; v1.y += o1.y;
            }
            *p0 = v0; *p1 = v1;
        }
    }
}

// ---------------- conv(k=3,pad=1) + silu + transpose: g_v[bt][h] -> g_vcT[h][bt] ----------------
// grid (TT/32, HH/32, BB), block 256
__global__ __launch_bounds__(256) void conv_t_silu_kernel(const float* __restrict__ w) {
    __shared__ float tile[34][33];
    const int b  = blockIdx.z;
    const int h0 = blockIdx.y * 32;
    const int t0 = blockIdx.x * 32;
    const int tid = threadIdx.x;

    #pragma unroll
    for (int i = tid; i < 34 * 32; i += 256) {
        int tt = i >> 5;            // 0..33  -> global t = t0 + tt - 1
        int hh = i & 31;
        int t  = t0 + tt - 1;
        float v = 0.f;
        if (t >= 0 && t < TT)
            v = g_v[((size_t)b * TT + t) * HH + h0 + hh];
        tile[tt][hh] = v;
    }
    __syncthreads();

    const int tl = tid & 31;        // local t
    const int hq = tid >> 5;        // 0..7
    #pragma unroll
    for (int j = 0; j < 4; j++) {
        int hh = hq * 4 + j;
        int h  = h0 + hh;
        float w0 = w[h * 3 + 0], w1 = w[h * 3 + 1], w2 = w[h * 3 + 2];
        float acc = tile[tl][hh] * w0;
        acc = fmaf(tile[tl + 1][hh], w1, acc);
        acc = fmaf(tile[tl + 2][hh], w2, acc);
        g_vcT[(size_t)h * BT + b * TT + t0 + tl] = silu_f(acc);
    }
}

// ---------------- dt1: dtr[bt][r] = relu(sum_h vcT[h][bt]*w[r][h] + bias[r]) ----------------
// grid BT/128, block 512: 4 h-quarters x 128 bt
__global__ __launch_bounds__(512) void dt1_kernel(const float* __restrict__ w,
                                                  const float* __restrict__ bias) {
    __shared__ float red[3][128][RR];   // quarters 1..3
    const int btl = threadIdx.x & 127;
    const int q   = threadIdx.x >> 7;   // 0..3
    const int bt  = blockIdx.x * 128 + btl;

    float acc[RR];
    #pragma unroll
    for (int r = 0; r < RR; r++) acc[r] = 0.f;

    const int hbase = q * 128;
    #pragma unroll 4
    for (int hh = 0; hh < 128; hh++) {
        int h = hbase + hh;
        float v = g_vcT[(size_t)h * BT + bt];
        #pragma unroll
        for (int r = 0; r < RR; r++) acc[r] = fmaf(v, w[r * HH + h], acc[r]);
    }
    if (q > 0) {
        #pragma unroll
        for (int r = 0; r < RR; r++) red[q - 1][btl][r] = acc[r];
    }
    __syncthreads();
    if (q == 0) {
        float4 o0, o1;
        float* op = (float*)&o0;
        #pragma unroll
        for (int r = 0; r < RR; r++) {
            float s = acc[r] + red[0][btl][r] + red[1][btl][r] + red[2][btl][r] + bias[r];
            if (r < 4) ((float*)&o0)[r] = fmaxf(s, 0.f);
            else       ((float*)&o1)[r - 4] = fmaxf(s, 0.f);
        }
        (void)op;
        *(float4*)(g_dtr + bt * RR)     = o0;
        *(float4*)(g_dtr + bt * RR + 4) = o1;
    }
}

// ---------------- dt2 + softplus -> dtT[h][bt] ----------------
// each thread: one h, 4 consecutive bt
__global__ void dt2_softplus_kernel(const float* __restrict__ w,
                                    const float* __restrict__ bias) {
    int gid = blockIdx.x * blockDim.x + threadIdx.x;   // < HH*BT/4
    int idx = gid * 4;                                  // [h][bt] linear
    int h   = idx >> 13;                                // /BT
    int bt0 = idx & (BT - 1);
    float wreg[RR];
    #pragma unroll
    for (int r = 0; r < RR; r++) wreg[r] = w[h * RR + r];
    float b0 = bias[h];
    float4 out;
    #pragma unroll
    for (int j = 0; j < 4; j++) {
        const float* dr = g_dtr + (size_t)(bt0 + j) * RR;
        float acc = b0;
        #pragma unroll
        for (int r = 0; r < RR; r++) acc = fmaf(dr[r], wreg[r], acc);
        ((float*)&out)[j] = (acc > 15.f) ? acc : log1pf(__expf(acc));
    }
    *(float4*)(g_dtT + idx) = out;
}

// ---------------- selective scan (streaming reads) -> y bf16 hi/lo [bt][h] ----------------
__global__ __launch_bounds__(128) void scan_kernel(const float* __restrict__ A_p,
                                                   const float* __restrict__ D_p) {
    int ch = blockIdx.x * 8 + (threadIdx.x >> 4);   // 0..4095
    int n  = threadIdx.x & 15;
    int b  = ch >> 9;
    int h  = ch & (HH - 1);
    float Ap = A_p[h * NN + n];
    float A  = -__expf(Ap);
    float invA = (fabsf(A) < 1e-5f) ? 1.f : (1.f / A);
    float Dp = D_p[h];
    const float* xrow = g_vcT + (size_t)h * BT + b * TT;
    const float* drow = g_dtT + (size_t)h * BT + b * TT;
    __nv_bfloat16* yh = g_yh + (size_t)(b * TT) * HH + h;
    __nv_bfloat16* yl = g_yl + (size_t)(b * TT) * HH + h;
    float state = 0.f;
    #pragma unroll 8
    for (int t = 0; t < TT; t++) {
        float dtv = drow[t];
        float x   = xrow[t];
        float discA = __expf(A * dtv);
        float discB = (discA - 1.f) * invA * dtv;
        state = fmaf(discA, state, discB * x);
        float part = state * Ap;
        part += __shfl_xor_sync(0xffffffffu, part, 8);
        part += __shfl_xor_sync(0xffffffffu, part, 4);
        part += __shfl_xor_sync(0xffffffffu, part, 2);
        part += __shfl_xor_sync(0xffffffffu, part, 1);
        if (n == 0) {
            float y = fmaf(Dp, x, part);
            __nv_bfloat16 hh, ll;
            split_bf16(y, hh, ll);
            yh[(size_t)t * HH] = hh;
            yl[(size_t)t * HH] = ll;
        }
    }
}

// ---------------- final LN (last token) + head1(silu) + head2 ----------------
__global__ void final_kernel(const float* __restrict__ fg,
                             const float* __restrict__ fb,
                             const float* __restrict__ w1,
                             const float* __restrict__ b1,
                             const float* __restrict__ w2,
                             const float* __restrict__ b2,
                             float* __restrict__ out) {
    int b = blockIdx.x;
    int tid = threadIdx.x;
    __shared__ float red1[8], red2[8];
    __shared__ float s_ln[DD];
    __shared__ float s_h1[DD];
    const float* row = g_h + (size_t)(b * TT + (TT - 1)) * DD;
    float v = row[tid];
    float mean = block_reduce_256(v, red1) * (1.f / 256.f);
    float c = v - mean;
    float var = block_reduce_256(c * c, red2) * (1.f / 256.f);
    s_ln[tid] = c * rsqrtf(var + 1e-5f) * fg[tid] + fb[tid];
    __syncthreads();
    float acc = b1[tid];
    const float* w1r = w1 + tid * DD;
    #pragma unroll 8
    for (int k = 0; k < DD; k++) acc = fmaf(s_ln[k], w1r[k], acc);
    s_h1[tid] = silu_f(acc);
    __syncthreads();
    if (tid < 96) {
        float a2 = b2[tid];
        const float* w2r = w2 + tid * DD;
        #pragma unroll 8
        for (int k = 0; k < DD; k++) a2 = fmaf(s_h1[k], w2r[k], a2);
        out[b * 96 + tid] = a2;
    }
}

// ---------------- launcher ----------------
extern "C" void kernel_launch(void* const* d_in, const int* in_sizes, int n_in,
                              void* d_out, int out_size) {
    const float* x      = (const float*)d_in[0];
    const float* emb_w  = (const float*)d_in[1];
    const float* emb_b  = (const float*)d_in[2];
    const float* norm_g = (const float*)d_in[3];
    const float* norm_b = (const float*)d_in[4];
    const float* in_w   = (const float*)d_in[5];
    const float* conv_w = (const float*)d_in[6];
    const float* A_p    = (const float*)d_in[7];
    const float* D_p    = (const float*)d_in[8];
    const float* dt1_w  = (const float*)d_in[9];
    const float* dt1_b  = (const float*)d_in[10];
    const float* dt2_w  = (const float*)d_in[11];
    const float* dt2_b  = (const float*)d_in[12];
    const float* out_w  = (const float*)d_in[13];
    const float* fin_g  = (const float*)d_in[14];
    const float* fin_b  = (const float*)d_in[15];
    const float* h1_w   = (const float*)d_in[16];
    const float* h1_b   = (const float*)d_in[17];
    const float* h2_w   = (const float*)d_in[18];
    const float* h2_b   = (const float*)d_in[19];
    float* out = (float*)d_out;

    float *ph, *pv;
    cudaGetSymbolAddress((void**)&ph,  g_h);
    cudaGetSymbolAddress((void**)&pv,  g_v);
    __nv_bfloat16 *plnh, *plnl, *pyh, *pyl, *piwh, *piwl, *powh, *powl;
    cudaGetSymbolAddress((void**)&plnh, g_lnh);
    cudaGetSymbolAddress((void**)&plnl, g_lnl);
    cudaGetSymbolAddress((void**)&pyh,  g_yh);
    cudaGetSymbolAddress((void**)&pyl,  g_yl);
    cudaGetSymbolAddress((void**)&piwh, g_iwh);
    cudaGetSymbolAddress((void**)&piwl, g_iwl);
    cudaGetSymbolAddress((void**)&powh, g_owh);
    cudaGetSymbolAddress((void**)&powl, g_owl);

    embed_kernel<<<BT, 256>>>(x, emb_w, emb_b);
    split_weights<<<(2 * NW) / 256, 256>>>(in_w, out_w);

    for (int l = 0; l < LL; l++) {
        ln_kernel<<<BT, 256>>>(norm_g + l * DD, norm_b + l * DD);

        // v = ln @ in_w[l]^T   (M=8192, N=512, K=256)
        gemm_bf16x3<<<dim3(HH / 64, BT / 128), 256>>>(
            plnh, plnl,
            piwh + (size_t)l * HH * DD, piwl + (size_t)l * HH * DD,
            pv, BT, HH, DD, 0);

        conv_t_silu_kernel<<<dim3(TT / 32, HH / 32, BB), 256>>>(
            conv_w + (size_t)l * HH * 3);

        dt1_kernel<<<BT / 128, 512>>>(dt1_w + (size_t)l * RR * HH, dt1_b + l * RR);
        dt2_softplus_kernel<<<(HH * BT / 4) / 256, 256>>>(
            dt2_w + (size_t)l * HH * RR, dt2_b + l * HH);

        scan_kernel<<<(BB * HH) / 8, 128>>>(A_p + (size_t)l * HH * NN,
                                            D_p + l * HH);

        // h += y @ out_w[l]^T  (M=8192, N=256, K=512)
        gemm_bf16x3<<<dim3(DD / 64, BT / 128), 256>>>(
            pyh, pyl,
            powh + (size_t)l * DD * HH, powl + (size_t)l * DD * HH,
            ph, BT, DD, HH, 1);
    }

    final_kernel<<<BB, 256>>>(fin_g, fin_b, h1_w, h1_b, h2_w, h2_b, out);
}

// round 5
// speedup vs baseline: 1.3811x; 1.0645x over previous
#include <cuda_runtime.h>
#include <cuda_bf16.h>
#include <cstdint>
#include <math.h>

// ---------------- problem constants ----------------
#define BB   8
#define TT   1024
#define DD   256
#define HH   512
#define NN   16
#define RR   8
#define LL   4
#define BT   (BB*TT)        // 8192
#define BTH  (BB*TT*HH)     // 4194304
#define BTD  (BB*TT*DD)     // 2097152
#define NW   (LL*HH*DD)     // 524288 (per weight tensor)

// ---------------- scratch (static device globals; no allocation) ----------------
__device__ float g_h  [BTD];
__device__ float g_v  [BTH];        // [bt][h]  (gemm1 output)
__device__ float g_vcT[BTH];        // [h][bt]  (conv+silu, transposed)
__device__ float g_dtT[BTH];        // [h][bt]  (softplus dt, transposed)
__device__ float g_dtr[BT*RR];
__device__ __nv_bfloat16 g_lnh[BTD], g_lnl[BTD];
__device__ __nv_bfloat16 g_yh [BTH], g_yl [BTH];   // [bt][h]
__device__ __nv_bfloat16 g_iwh[NW],  g_iwl[NW];
__device__ __nv_bfloat16 g_owh[NW],  g_owl[NW];

// ---------------- helpers ----------------
__device__ __forceinline__ float block_reduce_256(float v, float* red8) {
    #pragma unroll
    for (int o = 16; o; o >>= 1) v += __shfl_xor_sync(0xffffffffu, v, o);
    if ((threadIdx.x & 31) == 0) red8[threadIdx.x >> 5] = v;
    __syncthreads();
    float s = 0.f;
    #pragma unroll
    for (int i = 0; i < 8; i++) s += red8[i];
    return s;
}

__device__ __forceinline__ float silu_f(float x) {
    return x / (1.f + __expf(-x));
}

__device__ __forceinline__ void split_bf16(float v, __nv_bfloat16& h, __nv_bfloat16& l) {
    h = __float2bfloat16(v);
    l = __float2bfloat16(v - __bfloat162float(h));
}

__device__ __forceinline__ void ldsm4(unsigned int r[4], const void* p) {
    unsigned int a = (unsigned int)__cvta_generic_to_shared(p);
    asm volatile("ldmatrix.sync.aligned.m8n8.x4.shared.b16 {%0,%1,%2,%3}, [%4];"
                 : "=r"(r[0]), "=r"(r[1]), "=r"(r[2]), "=r"(r[3]) : "r"(a));
}

__device__ __forceinline__ void mma_bf16(float c[4], const unsigned int a[4],
                                         unsigned int b0, unsigned int b1) {
    asm volatile(
        "mma.sync.aligned.m16n8k16.row.col.f32.bf16.bf16.f32 "
        "{%0,%1,%2,%3},{%4,%5,%6,%7},{%8,%9},{%0,%1,%2,%3};"
        : "+f"(c[0]), "+f"(c[1]), "+f"(c[2]), "+f"(c[3])
        : "r"(a[0]), "r"(a[1]), "r"(a[2]), "r"(a[3]), "r"(b0), "r"(b1));
}

// ---------------- embed + positional encoding ----------------
__global__ void embed_kernel(const float* __restrict__ x,
                             const float* __restrict__ emb_w,
                             const float* __restrict__ emb_b) {
    int bt = blockIdx.x;
    int d  = threadIdx.x;
    __shared__ float sx[32];
    if (d < 32) sx[d] = x[bt * 32 + d];
    __syncthreads();
    float acc = emb_b[d];
    const float* w = emb_w + d * 32;
    #pragma unroll
    for (int i = 0; i < 32; i++) acc = fmaf(sx[i], w[i], acc);
    int t = bt & (TT - 1);
    int k2 = d & ~1;
    float div = __expf((float)k2 * (-9.210340371976184f / 256.0f));
    float ang = (float)t * div;
    acc += (d & 1) ? cosf(ang) : sinf(ang);
    g_h[bt * DD + d] = acc;
}

// ---------------- weight split: fp32 -> bf16 hi/lo ----------------
__global__ void split_weights(const float* __restrict__ in_w,
                              const float* __restrict__ out_w) {
    int i = blockIdx.x * 256 + threadIdx.x;
    if (i < NW) {
        split_bf16(in_w[i], g_iwh[i], g_iwl[i]);
    } else {
        int j = i - NW;
        split_bf16(out_w[j], g_owh[j], g_owl[j]);
    }
}

// ---------------- layernorm over D=256 -> bf16 hi/lo ----------------
__global__ void ln_kernel(const float* __restrict__ g,
                          const float* __restrict__ b) {
    __shared__ float red1[8], red2[8];
    int row = blockIdx.x;
    int d   = threadIdx.x;
    float v = g_h[row * DD + d];
    float mean = block_reduce_256(v, red1) * (1.f / 256.f);
    float c = v - mean;
    float var = block_reduce_256(c * c, red2) * (1.f / 256.f);
    float o = c * rsqrtf(var + 1e-5f) * g[d] + b[d];
    split_bf16(o, g_lnh[row * DD + d], g_lnl[row * DD + d]);
}

// ---------------- bf16x3 tensor-core GEMM ----------------
// C[M,N] (+)= A[M,K] * W[N,K]^T, A/W given as bf16 (hi,lo) pairs.
#define PADK 40
__global__ __launch_bounds__(256) void gemm_bf16x3(
    const __nv_bfloat16* __restrict__ Ah, const __nv_bfloat16* __restrict__ Al,
    const __nv_bfloat16* __restrict__ Wh, const __nv_bfloat16* __restrict__ Wl,
    float* __restrict__ C, int M, int N, int K, int accumulate)
{
    __shared__ __nv_bfloat16 sAh[128][PADK], sAl[128][PADK];
    __shared__ __nv_bfloat16 sWh[64][PADK],  sWl[64][PADK];

    const int tid  = threadIdx.x;
    const int lane = tid & 31;
    const int wid  = tid >> 5;
    const int wm   = (wid & 3) * 32;
    const int wn   = (wid >> 2) * 32;
    const int bm   = blockIdx.y * 128;
    const int bn   = blockIdx.x * 64;

    float acc[2][4][4];
    #pragma unroll
    for (int a = 0; a < 2; a++)
        #pragma unroll
        for (int b = 0; b < 4; b++)
            #pragma unroll
            for (int c = 0; c < 4; c++) acc[a][b][c] = 0.f;

    const int lrow = tid >> 2;
    const int lcol = (tid & 3) * 8;

    const int a_row = lane & 15;
    const int a_col = (lane >> 4) << 3;
    const int bq    = lane >> 3;
    const int b_row = (lane & 7) + ((bq >> 1) << 3);
    const int b_col = (bq & 1) << 3;

    for (int kt = 0; kt < K; kt += 32) {
        const __nv_bfloat16* pA = Ah + (size_t)(bm + lrow) * K + kt + lcol;
        const __nv_bfloat16* pa = Al + (size_t)(bm + lrow) * K + kt + lcol;
        *(uint4*)&sAh[lrow     ][lcol] = *(const uint4*)pA;
        *(uint4*)&sAh[lrow + 64][lcol] = *(const uint4*)(pA + (size_t)64 * K);
        *(uint4*)&sAl[lrow     ][lcol] = *(const uint4*)pa;
        *(uint4*)&sAl[lrow + 64][lcol] = *(const uint4*)(pa + (size_t)64 * K);
        const __nv_bfloat16* pW = Wh + (size_t)(bn + lrow) * K + kt + lcol;
        const __nv_bfloat16* pw = Wl + (size_t)(bn + lrow) * K + kt + lcol;
        *(uint4*)&sWh[lrow][lcol] = *(const uint4*)pW;
        *(uint4*)&sWl[lrow][lcol] = *(const uint4*)pw;
        __syncthreads();

        #pragma unroll
        for (int ks = 0; ks < 2; ks++) {
            const int k0 = ks * 16;
            unsigned int ah[2][4], al[2][4];
            #pragma unroll
            for (int mt = 0; mt < 2; mt++) {
                ldsm4(ah[mt], &sAh[wm + mt * 16 + a_row][k0 + a_col]);
                ldsm4(al[mt], &sAl[wm + mt * 16 + a_row][k0 + a_col]);
            }
            unsigned int bh[2][4], bl[2][4];
            #pragma unroll
            for (int nb = 0; nb < 2; nb++) {
                ldsm4(bh[nb], &sWh[wn + nb * 16 + b_row][k0 + b_col]);
                ldsm4(bl[nb], &sWl[wn + nb * 16 + b_row][k0 + b_col]);
            }
            #pragma unroll
            for (int mt = 0; mt < 2; mt++) {
                #pragma unroll
                for (int nt = 0; nt < 4; nt++) {
                    const int nb = nt >> 1, hf = (nt & 1) * 2;
                    mma_bf16(acc[mt][nt], ah[mt], bh[nb][hf], bh[nb][hf + 1]);
                    mma_bf16(acc[mt][nt], ah[mt], bl[nb][hf], bl[nb][hf + 1]);
                    mma_bf16(acc[mt][nt], al[mt], bh[nb][hf], bh[nb][hf + 1]);
                }
            }
        }
        __syncthreads();
    }

    const int cg = lane >> 2;
    const int ct = (lane & 3) * 2;
    #pragma unroll
    for (int mt = 0; mt < 2; mt++) {
        #pragma unroll
        for (int nt = 0; nt < 4; nt++) {
            int r0 = bm + wm + mt * 16 + cg;
            int c0 = bn + wn + nt * 8 + ct;
            float2* p0 = (float2*)(C + (size_t)r0 * N + c0);
            float2* p1 = (float2*)(C + (size_t)(r0 + 8) * N + c0);
            float2 v0 = make_float2(acc[mt][nt][0], acc[mt][nt][1]);
            float2 v1 = make_float2(acc[mt][nt][2], acc[mt][nt][3]);
            if (accumulate) {
                float2 o0 = *p0, o1 = *p1;
                v0.x += o0.x; v0.y += o0.y;
                v1.x += o1.x; v1.y += o1.y;
            }
            *p0 = v0; *p1 = v1;
        }
    }
}

// ---------------- conv(k=3,pad=1) + silu + transpose: g_v[bt][h] -> g_vcT[h][bt] ----------------
__global__ __launch_bounds__(256) void conv_t_silu_kernel(const float* __restrict__ w) {
    __shared__ float tile[34][33];
    const int b  = blockIdx.z;
    const int h0 = blockIdx.y * 32;
    const int t0 = blockIdx.x * 32;
    const int tid = threadIdx.x;

    #pragma unroll
    for (int i = tid; i < 34 * 32; i += 256) {
        int tt = i >> 5;
        int hh = i & 31;
        int t  = t0 + tt - 1;
        float v = 0.f;
        if (t >= 0 && t < TT)
            v = g_v[((size_t)b * TT + t) * HH + h0 + hh];
        tile[tt][hh] = v;
    }
    __syncthreads();

    const int tl = tid & 31;
    const int hq = tid >> 5;
    #pragma unroll
    for (int j = 0; j < 4; j++) {
        int hh = hq * 4 + j;
        int h  = h0 + hh;
        float w0 = w[h * 3 + 0], w1 = w[h * 3 + 1], w2 = w[h * 3 + 2];
        float acc = tile[tl][hh] * w0;
        acc = fmaf(tile[tl + 1][hh], w1, acc);
        acc = fmaf(tile[tl + 2][hh], w2, acc);
        g_vcT[(size_t)h * BT + b * TT + t0 + tl] = silu_f(acc);
    }
}

// ---------------- dt1 ----------------
__global__ __launch_bounds__(512) void dt1_kernel(const float* __restrict__ w,
                                                  const float* __restrict__ bias) {
    __shared__ float red[3][128][RR];
    const int btl = threadIdx.x & 127;
    const int q   = threadIdx.x >> 7;
    const int bt  = blockIdx.x * 128 + btl;

    float acc[RR];
    #pragma unroll
    for (int r = 0; r < RR; r++) acc[r] = 0.f;

    const int hbase = q * 128;
    #pragma unroll 4
    for (int hh = 0; hh < 128; hh++) {
        int h = hbase + hh;
        float v = g_vcT[(size_t)h * BT + bt];
        #pragma unroll
        for (int r = 0; r < RR; r++) acc[r] = fmaf(v, w[r * HH + h], acc[r]);
    }
    if (q > 0) {
        #pragma unroll
        for (int r = 0; r < RR; r++) red[q - 1][btl][r] = acc[r];
    }
    __syncthreads();
    if (q == 0) {
        float4 o0, o1;
        #pragma unroll
        for (int r = 0; r < RR; r++) {
            float s = acc[r] + red[0][btl][r] + red[1][btl][r] + red[2][btl][r] + bias[r];
            if (r < 4) ((float*)&o0)[r] = fmaxf(s, 0.f);
            else       ((float*)&o1)[r - 4] = fmaxf(s, 0.f);
        }
        *(float4*)(g_dtr + bt * RR)     = o0;
        *(float4*)(g_dtr + bt * RR + 4) = o1;
    }
}

// ---------------- dt2 + softplus -> dtT[h][bt] ----------------
__global__ void dt2_softplus_kernel(const float* __restrict__ w,
                                    const float* __restrict__ bias) {
    int gid = blockIdx.x * blockDim.x + threadIdx.x;
    int idx = gid * 4;
    int h   = idx >> 13;
    int bt0 = idx & (BT - 1);
    float wreg[RR];
    #pragma unroll
    for (int r = 0; r < RR; r++) wreg[r] = w[h * RR + r];
    float b0 = bias[h];
    float4 out;
    #pragma unroll
    for (int j = 0; j < 4; j++) {
        const float* dr = g_dtr + (size_t)(bt0 + j) * RR;
        float acc = b0;
        #pragma unroll
        for (int r = 0; r < RR; r++) acc = fmaf(dr[r], wreg[r], acc);
        ((float*)&out)[j] = (acc > 15.f) ? acc : log1pf(__expf(acc));
    }
    *(float4*)(g_dtT + idx) = out;
}

// ---------------- selective scan: streaming reads, smem-staged coalesced y stores ----------------
// block = 128 threads = 8 consecutive channels (same b) x 16 n-lanes
__global__ __launch_bounds__(128) void scan_kernel(const float* __restrict__ A_p,
                                                   const float* __restrict__ D_p) {
    __shared__ __nv_bfloat16 s_yh[32][8], s_yl[32][8];
    const int cid = threadIdx.x >> 4;           // 0..7
    const int n   = threadIdx.x & 15;
    const int ch  = blockIdx.x * 8 + cid;       // 0..4095
    const int b   = ch >> 9;
    const int h   = ch & (HH - 1);
    const int hblk = (blockIdx.x * 8) & (HH - 1);

    float Ap = A_p[h * NN + n];
    float A  = -__expf(Ap);
    float invA = (fabsf(A) < 1e-5f) ? 1.f : (1.f / A);
    float Dp = D_p[h];
    const float* xrow = g_vcT + (size_t)h * BT + b * TT;
    const float* drow = g_dtT + (size_t)h * BT + b * TT;

    const int fl_t = threadIdx.x >> 2;          // 0..31
    const int fl_h = (threadIdx.x & 3) * 2;     // 0,2,4,6

    float state = 0.f;
    for (int tb = 0; tb < TT; tb += 32) {
        #pragma unroll 8
        for (int tt = 0; tt < 32; tt++) {
            int t = tb + tt;
            float dtv = drow[t];
            float x   = xrow[t];
            float discA = __expf(A * dtv);
            float discB = (discA - 1.f) * invA * dtv;
            state = fmaf(discA, state, discB * x);
            float part = state * Ap;
            part += __shfl_xor_sync(0xffffffffu, part, 8);
            part += __shfl_xor_sync(0xffffffffu, part, 4);
            part += __shfl_xor_sync(0xffffffffu, part, 2);
            part += __shfl_xor_sync(0xffffffffu, part, 1);
            if (n == 0) {
                float y = fmaf(Dp, x, part);
                __nv_bfloat16 hh, ll;
                split_bf16(y, hh, ll);
                s_yh[tt][cid] = hh;
                s_yl[tt][cid] = ll;
            }
        }
        __syncthreads();
        size_t base = (size_t)(b * TT + tb + fl_t) * HH + hblk + fl_h;
        *(unsigned int*)(g_yh + base) = *(unsigned int*)&s_yh[fl_t][fl_h];
        *(unsigned int*)(g_yl + base) = *(unsigned int*)&s_yl[fl_t][fl_h];
        __syncthreads();
    }
}

// ---------------- final LN (last token) + head1(silu) + head2 ----------------
__global__ void final_kernel(const float* __restrict__ fg,
                             const float* __restrict__ fb,
                             const float* __restrict__ w1,
                             const float* __restrict__ b1,
                             const float* __restrict__ w2,
                             const float* __restrict__ b2,
                             float* __restrict__ out) {
    int b = blockIdx.x;
    int tid = threadIdx.x;
    __shared__ float red1[8], red2[8];
    __shared__ float s_ln[DD];
    __shared__ float s_h1[DD];
    const float* row = g_h + (size_t)(b * TT + (TT - 1)) * DD;
    float v = row[tid];
    float mean = block_reduce_256(v, red1) * (1.f / 256.f);
    float c = v - mean;
    float var = block_reduce_256(c * c, red2) * (1.f / 256.f);
    s_ln[tid] = c * rsqrtf(var + 1e-5f) * fg[tid] + fb[tid];
    __syncthreads();
    float acc = b1[tid];
    const float* w1r = w1 + tid * DD;
    #pragma unroll 8
    for (int k = 0; k < DD; k++) acc = fmaf(s_ln[k], w1r[k], acc);
    s_h1[tid] = silu_f(acc);
    __syncthreads();
    if (tid < 96) {
        float a2 = b2[tid];
        const float* w2r = w2 + tid * DD;
        #pragma unroll 8
        for (int k = 0; k < DD; k++) a2 = fmaf(s_h1[k], w2r[k], a2);
        out[b * 96 + tid] = a2;
    }
}

// ---------------- launcher ----------------
extern "C" void kernel_launch(void* const* d_in, const int* in_sizes, int n_in,
                              void* d_out, int out_size) {
    const float* x      = (const float*)d_in[0];
    const float* emb_w  = (const float*)d_in[1];
    const float* emb_b  = (const float*)d_in[2];
    const float* norm_g = (const float*)d_in[3];
    const float* norm_b = (const float*)d_in[4];
    const float* in_w   = (const float*)d_in[5];
    const float* conv_w = (const float*)d_in[6];
    const float* A_p    = (const float*)d_in[7];
    const float* D_p    = (const float*)d_in[8];
    const float* dt1_w  = (const float*)d_in[9];
    const float* dt1_b  = (const float*)d_in[10];
    const float* dt2_w  = (const float*)d_in[11];
    const float* dt2_b  = (const float*)d_in[12];
    const float* out_w  = (const float*)d_in[13];
    const float* fin_g  = (const float*)d_in[14];
    const float* fin_b  = (const float*)d_in[15];
    const float* h1_w   = (const float*)d_in[16];
    const float* h1_b   = (const float*)d_in[17];
    const float* h2_w   = (const float*)d_in[18];
    const float* h2_b   = (const float*)d_in[19];
    float* out = (float*)d_out;

    float *ph, *pv;
    cudaGetSymbolAddress((void**)&ph,  g_h);
    cudaGetSymbolAddress((void**)&pv,  g_v);
    __nv_bfloat16 *plnh, *plnl, *pyh, *pyl, *piwh, *piwl, *powh, *powl;
    cudaGetSymbolAddress((void**)&plnh, g_lnh);
    cudaGetSymbolAddress((void**)&plnl, g_lnl);
    cudaGetSymbolAddress((void**)&pyh,  g_yh);
    cudaGetSymbolAddress((void**)&pyl,  g_yl);
    cudaGetSymbolAddress((void**)&piwh, g_iwh);
    cudaGetSymbolAddress((void**)&piwl, g_iwl);
    cudaGetSymbolAddress((void**)&powh, g_owh);
    cudaGetSymbolAddress((void**)&powl, g_owl);

    embed_kernel<<<BT, 256>>>(x, emb_w, emb_b);
    split_weights<<<(2 * NW) / 256, 256>>>(in_w, out_w);

    for (int l = 0; l < LL; l++) {
        ln_kernel<<<BT, 256>>>(norm_g + l * DD, norm_b + l * DD);

        gemm_bf16x3<<<dim3(HH / 64, BT / 128), 256>>>(
            plnh, plnl,
            piwh + (size_t)l * HH * DD, piwl + (size_t)l * HH * DD,
            pv, BT, HH, DD, 0);

        conv_t_silu_kernel<<<dim3(TT / 32, HH / 32, BB), 256>>>(
            conv_w + (size_t)l * HH * 3);

        dt1_kernel<<<BT / 128, 512>>>(dt1_w + (size_t)l * RR * HH, dt1_b + l * RR);
        dt2_softplus_kernel<<<(HH * BT / 4) / 256, 256>>>(
            dt2_w + (size_t)l * HH * RR, dt2_b + l * HH);

        scan_kernel<<<(BB * HH) / 8, 128>>>(A_p + (size_t)l * HH * NN,
                                            D_p + l * HH);

        gemm_bf16x3<<<dim3(DD / 64, BT / 128), 256>>>(
            pyh, pyl,
            powh + (size_t)l * DD * HH, powl + (size_t)l * DD * HH,
            ph, BT, DD, HH, 1);
    }

    final_kernel<<<BB, 256>>>(fin_g, fin_b, h1_w, h1_b, h2_w, h2_b, out);
}

// round 6
// speedup vs baseline: 1.5431x; 1.1173x over previous
#include <cuda_runtime.h>
#include <cuda_bf16.h>
#include <cstdint>
#include <math.h>

typedef __nv_bfloat16 bf16;

// ---------------- problem constants ----------------
#define BB   8
#define TT   1024
#define DD   256
#define HH   512
#define NN   16
#define RR   8
#define LL   4
#define BT   (BB*TT)        // 8192
#define BTH  (BB*TT*HH)     // 4194304
#define BTD  (BB*TT*DD)     // 2097152
#define NW   (LL*HH*DD)     // 524288

#define GRID_PERSIST 296    // 148 SMs x 2 blocks, all resident in one wave

// ---------------- scratch (static device globals; no allocation) ----------------
__device__ float g_h  [BTD];
__device__ float g_v  [BTH];        // [bt][h]
__device__ float g_vcT[BTH];        // [h][bt]
__device__ float g_dtT[BTH];        // [h][bt]
__device__ bf16 g_lnh[BTD], g_lnl[BTD];
__device__ bf16 g_yh [BTH], g_yl [BTH];   // [bt][h]
__device__ bf16 g_iwh[NW],  g_iwl[NW];
__device__ bf16 g_owh[NW],  g_owl[NW];

// ---------------- grid-wide spin barrier ----------------
__device__ unsigned int g_bar_cnt;
__device__ unsigned int g_bar_gen;

__device__ __forceinline__ void grid_barrier() {
    __syncthreads();
    if (threadIdx.x == 0) {
        __threadfence();
        unsigned int gen = atomicAdd(&g_bar_gen, 0u);
        unsigned int arrived = atomicAdd(&g_bar_cnt, 1u);
        if (arrived == gridDim.x - 1) {
            g_bar_cnt = 0;
            __threadfence();
            atomicAdd(&g_bar_gen, 1u);
        } else {
            while (atomicAdd(&g_bar_gen, 0u) == gen) __nanosleep(128);
        }
        __threadfence();
    }
    __syncthreads();
}

// ---------------- helpers ----------------
__device__ __forceinline__ float silu_f(float x) {
    return x / (1.f + __expf(-x));
}

__device__ __forceinline__ void split_bf16(float v, bf16& h, bf16& l) {
    h = __float2bfloat16(v);
    l = __float2bfloat16(v - __bfloat162float(h));
}

__device__ __forceinline__ unsigned int pk2(bf16 a, bf16 b) {
    return (unsigned int)__bfloat16_as_ushort(a) |
           ((unsigned int)__bfloat16_as_ushort(b) << 16);
}

__device__ __forceinline__ void ldsm4(unsigned int r[4], const void* p) {
    unsigned int a = (unsigned int)__cvta_generic_to_shared(p);
    asm volatile("ldmatrix.sync.aligned.m8n8.x4.shared.b16 {%0,%1,%2,%3}, [%4];"
                 : "=r"(r[0]), "=r"(r[1]), "=r"(r[2]), "=r"(r[3]) : "r"(a));
}

__device__ __forceinline__ void mma_bf16(float c[4], const unsigned int a[4],
                                         unsigned int b0, unsigned int b1) {
    asm volatile(
        "mma.sync.aligned.m16n8k16.row.col.f32.bf16.bf16.f32 "
        "{%0,%1,%2,%3},{%4,%5,%6,%7},{%8,%9},{%0,%1,%2,%3};"
        : "+f"(c[0]), "+f"(c[1]), "+f"(c[2]), "+f"(c[3])
        : "r"(a[0]), "r"(a[1]), "r"(a[2]), "r"(a[3]), "r"(b0), "r"(b1));
}

// ---------------- smem union layout (31 KB) ----------------
#define PADK 40
#define SMEM_BYTES 30976
// gemm:  sAh @0 (10240), sAl @10240 (10240), sWh @20480 (5120), sWl @25600 (5120)
// conv:  float tile[34][33] @0 (4488)
// dt:    float red[128][9] @0 (4608), float dtr[128][9] @4608 (4608)
// scan:  bf16 yh[32][16] @0 (1024), bf16 yl[32][16] @1024 (1024)

// ---------------- gemm tile (device fn) ----------------
__device__ void gemm_tile(char* s_raw,
    const bf16* __restrict__ Ah, const bf16* __restrict__ Al,
    const bf16* __restrict__ Wh, const bf16* __restrict__ Wl,
    float* __restrict__ C, int N, int K, int accumulate, int bm, int bn)
{
    bf16 (*sAh)[PADK] = (bf16(*)[PADK])(s_raw);
    bf16 (*sAl)[PADK] = (bf16(*)[PADK])(s_raw + 10240);
    bf16 (*sWh)[PADK] = (bf16(*)[PADK])(s_raw + 20480);
    bf16 (*sWl)[PADK] = (bf16(*)[PADK])(s_raw + 25600);

    const int tid  = threadIdx.x;
    const int lane = tid & 31;
    const int wid  = tid >> 5;
    const int wm   = (wid & 3) * 32;
    const int wn   = (wid >> 2) * 32;

    float acc[2][4][4];
    #pragma unroll
    for (int a = 0; a < 2; a++)
        #pragma unroll
        for (int b = 0; b < 4; b++)
            #pragma unroll
            for (int c = 0; c < 4; c++) acc[a][b][c] = 0.f;

    const int lrow = tid >> 2;
    const int lcol = (tid & 3) * 8;

    const int a_row = lane & 15;
    const int a_col = (lane >> 4) << 3;
    const int bq    = lane >> 3;
    const int b_row = (lane & 7) + ((bq >> 1) << 3);
    const int b_col = (bq & 1) << 3;

    for (int kt = 0; kt < K; kt += 32) {
        const bf16* pA = Ah + (size_t)(bm + lrow) * K + kt + lcol;
        const bf16* pa = Al + (size_t)(bm + lrow) * K + kt + lcol;
        *(uint4*)&sAh[lrow     ][lcol] = *(const uint4*)pA;
        *(uint4*)&sAh[lrow + 64][lcol] = *(const uint4*)(pA + (size_t)64 * K);
        *(uint4*)&sAl[lrow     ][lcol] = *(const uint4*)pa;
        *(uint4*)&sAl[lrow + 64][lcol] = *(const uint4*)(pa + (size_t)64 * K);
        const bf16* pW = Wh + (size_t)(bn + lrow) * K + kt + lcol;
        const bf16* pw = Wl + (size_t)(bn + lrow) * K + kt + lcol;
        *(uint4*)&sWh[lrow][lcol] = *(const uint4*)pW;
        *(uint4*)&sWl[lrow][lcol] = *(const uint4*)pw;
        __syncthreads();

        #pragma unroll
        for (int ks = 0; ks < 2; ks++) {
            const int k0 = ks * 16;
            unsigned int ah[2][4], al[2][4];
            #pragma unroll
            for (int mt = 0; mt < 2; mt++) {
                ldsm4(ah[mt], &sAh[wm + mt * 16 + a_row][k0 + a_col]);
                ldsm4(al[mt], &sAl[wm + mt * 16 + a_row][k0 + a_col]);
            }
            unsigned int bh[2][4], bl[2][4];
            #pragma unroll
            for (int nb = 0; nb < 2; nb++) {
                ldsm4(bh[nb], &sWh[wn + nb * 16 + b_row][k0 + b_col]);
                ldsm4(bl[nb], &sWl[wn + nb * 16 + b_row][k0 + b_col]);
            }
            #pragma unroll
            for (int mt = 0; mt < 2; mt++) {
                #pragma unroll
                for (int nt = 0; nt < 4; nt++) {
                    const int nb = nt >> 1, hf = (nt & 1) * 2;
                    mma_bf16(acc[mt][nt], ah[mt], bh[nb][hf], bh[nb][hf + 1]);
                    mma_bf16(acc[mt][nt], ah[mt], bl[nb][hf], bl[nb][hf + 1]);
                    mma_bf16(acc[mt][nt], al[mt], bh[nb][hf], bh[nb][hf + 1]);
                }
            }
        }
        __syncthreads();
    }

    const int cg = lane >> 2;
    const int ct = (lane & 3) * 2;
    #pragma unroll
    for (int mt = 0; mt < 2; mt++) {
        #pragma unroll
        for (int nt = 0; nt < 4; nt++) {
            int r0 = bm + wm + mt * 16 + cg;
            int c0 = bn + wn + nt * 8 + ct;
            float2* p0 = (float2*)(C + (size_t)r0 * N + c0);
            float2* p1 = (float2*)(C + (size_t)(r0 + 8) * N + c0);
            float2 v0 = make_float2(acc[mt][nt][0], acc[mt][nt][1]);
            float2 v1 = make_float2(acc[mt][nt][2], acc[mt][nt][3]);
            if (accumulate) {
                float2 o0 = *p0, o1 = *p1;
                v0.x += o0.x; v0.y += o0.y;
                v1.x += o1.x; v1.y += o1.y;
            }
            *p0 = v0; *p1 = v1;
        }
    }
}

// ---------------- merged embed + pos-encoding + weight split (1 node) ----------------
__global__ void emb_split_kernel(const float* __restrict__ x,
                                 const float* __restrict__ emb_w,
                                 const float* __restrict__ emb_b,
                                 const float* __restrict__ in_w,
                                 const float* __restrict__ out_w) {
    if (blockIdx.x < BT) {
        int bt = blockIdx.x;
        int d  = threadIdx.x;
        __shared__ float sx[32];
        if (d < 32) sx[d] = x[bt * 32 + d];
        __syncthreads();
        float acc = emb_b[d];
        const float* w = emb_w + d * 32;
        #pragma unroll
        for (int i = 0; i < 32; i++) acc = fmaf(sx[i], w[i], acc);
        int t = bt & (TT - 1);
        int k2 = d & ~1;
        float div = __expf((float)k2 * (-9.210340371976184f / 256.0f));
        float ang = (float)t * div;
        acc += (d & 1) ? cosf(ang) : sinf(ang);
        g_h[bt * DD + d] = acc;
    } else {
        int i = (blockIdx.x - BT) * 256 + threadIdx.x;
        if (i < NW) {
            split_bf16(in_w[i], g_iwh[i], g_iwl[i]);
        } else {
            int j = i - NW;
            split_bf16(out_w[j], g_owh[j], g_owl[j]);
        }
    }
}

// ---------------- persistent per-layer kernel (6 phases, 5 grid barriers) ----------------
__global__ __launch_bounds__(256, 2) void layer_kernel(
    const float* __restrict__ ng,  const float* __restrict__ nb_,
    const float* __restrict__ cw,
    const float* __restrict__ Apw, const float* __restrict__ Dpw,
    const float* __restrict__ w1,  const float* __restrict__ b1,
    const float* __restrict__ w2,  const float* __restrict__ b2,
    const bf16* __restrict__ iwh,  const bf16* __restrict__ iwl,
    const bf16* __restrict__ owh,  const bf16* __restrict__ owl)
{
    __shared__ __align__(16) char s_raw[SMEM_BYTES];
    const int bid = blockIdx.x;
    const int nbk = gridDim.x;
    const int tid = threadIdx.x;
    const int lane = tid & 31;
    const int warp = tid >> 5;

    // ---- phase 0: layernorm (warp per row) -> g_lnh/g_lnl ----
    for (int row = bid * 8 + warp; row < BT; row += nbk * 8) {
        const float* p = g_h + (size_t)row * DD + lane * 8;
        float4 a = *(const float4*)p;
        float4 c = *(const float4*)(p + 4);
        float v[8] = {a.x, a.y, a.z, a.w, c.x, c.y, c.z, c.w};
        float s = 0.f;
        #pragma unroll
        for (int j = 0; j < 8; j++) s += v[j];
        #pragma unroll
        for (int o = 16; o; o >>= 1) s += __shfl_xor_sync(0xffffffffu, s, o);
        float mean = s * (1.f / 256.f);
        float vv = 0.f;
        #pragma unroll
        for (int j = 0; j < 8; j++) { float d0 = v[j] - mean; vv += d0 * d0; }
        #pragma unroll
        for (int o = 16; o; o >>= 1) vv += __shfl_xor_sync(0xffffffffu, vv, o);
        float rstd = rsqrtf(vv * (1.f / 256.f) + 1e-5f);
        float4 gg0 = *(const float4*)(ng + lane * 8);
        float4 gg1 = *(const float4*)(ng + lane * 8 + 4);
        float4 bb0 = *(const float4*)(nb_ + lane * 8);
        float4 bb1 = *(const float4*)(nb_ + lane * 8 + 4);
        float gv[8] = {gg0.x, gg0.y, gg0.z, gg0.w, gg1.x, gg1.y, gg1.z, gg1.w};
        float bv[8] = {bb0.x, bb0.y, bb0.z, bb0.w, bb1.x, bb1.y, bb1.z, bb1.w};
        bf16 oh[8], ol[8];
        #pragma unroll
        for (int j = 0; j < 8; j++) {
            float o = (v[j] - mean) * rstd * gv[j] + bv[j];
            split_bf16(o, oh[j], ol[j]);
        }
        uint4 uh, ul;
        uh.x = pk2(oh[0], oh[1]); uh.y = pk2(oh[2], oh[3]);
        uh.z = pk2(oh[4], oh[5]); uh.w = pk2(oh[6], oh[7]);
        ul.x = pk2(ol[0], ol[1]); ul.y = pk2(ol[2], ol[3]);
        ul.z = pk2(ol[4], ol[5]); ul.w = pk2(ol[6], ol[7]);
        *(uint4*)(g_lnh + (size_t)row * DD + lane * 8) = uh;
        *(uint4*)(g_lnl + (size_t)row * DD + lane * 8) = ul;
    }
    grid_barrier();

    // ---- phase 1: gemm1  v[bt][h] = ln @ in_w^T  (512 tiles: 64 m x 8 n) ----
    for (int t = bid; t < 512; t += nbk)
        gemm_tile(s_raw, g_lnh, g_lnl, iwh, iwl, g_v, HH, DD, 0,
                  (t >> 3) * 128, (t & 7) * 64);
    grid_barrier();

    // ---- phase 2: conv(k=3) + silu + transpose -> g_vcT[h][bt] (4096 tasks) ----
    {
        float (*tile)[33] = (float(*)[33])(s_raw);
        for (int task = bid; task < BB * 16 * 32; task += nbk) {
            const int b  = task >> 9;
            const int h0 = ((task >> 5) & 15) * 32;
            const int t0 = (task & 31) * 32;
            #pragma unroll
            for (int i = tid; i < 34 * 32; i += 256) {
                int tt = i >> 5;
                int hh = i & 31;
                int t  = t0 + tt - 1;
                float v = 0.f;
                if (t >= 0 && t < TT)
                    v = g_v[((size_t)b * TT + t) * HH + h0 + hh];
                tile[tt][hh] = v;
            }
            __syncthreads();
            const int tl = tid & 31;
            const int hq = tid >> 5;
            #pragma unroll
            for (int j = 0; j < 4; j++) {
                int hh = hq * 4 + j;
                int h  = h0 + hh;
                float w0 = cw[h * 3 + 0], w1v = cw[h * 3 + 1], w2v = cw[h * 3 + 2];
                float acc = tile[tl][hh] * w0;
                acc = fmaf(tile[tl + 1][hh], w1v, acc);
                acc = fmaf(tile[tl + 2][hh], w2v, acc);
                g_vcT[(size_t)h * BT + b * TT + t0 + tl] = silu_f(acc);
            }
            __syncthreads();
        }
    }
    grid_barrier();

    // ---- phase 3: dt1 + dt2 fused -> g_dtT[h][bt] (64 tasks of 128 bt) ----
    {
        float (*red)[9]  = (float(*)[9])(s_raw);
        float (*dtrs)[9] = (float(*)[9])(s_raw + 4608);
        const int btl = tid & 127;
        const int q   = tid >> 7;       // 0..1 (h-halves)
        for (int task = bid; task < BT / 128; task += nbk) {
            const int bt0 = task * 128;
            float acc[RR];
            #pragma unroll
            for (int r = 0; r < RR; r++) acc[r] = 0.f;
            const int hbase = q * 256;
            #pragma unroll 4
            for (int hh = 0; hh < 256; hh++) {
                int h = hbase + hh;
                float v = g_vcT[(size_t)h * BT + bt0 + btl];
                #pragma unroll
                for (int r = 0; r < RR; r++) acc[r] = fmaf(v, w1[r * HH + h], acc[r]);
            }
            if (q == 1) {
                #pragma unroll
                for (int r = 0; r < RR; r++) red[btl][r] = acc[r];
            }
            __syncthreads();
            if (q == 0) {
                #pragma unroll
                for (int r = 0; r < RR; r++)
                    dtrs[btl][r] = fmaxf(acc[r] + red[btl][r] + b1[r], 0.f);
            }
            __syncthreads();
            // dt2 + softplus for all 512 h, this bt tile
            for (int hh = q; hh < HH; hh += 2) {
                float wreg[RR];
                #pragma unroll
                for (int r = 0; r < RR; r++) wreg[r] = w2[hh * RR + r];
                float a2 = b2[hh];
                #pragma unroll
                for (int r = 0; r < RR; r++) a2 = fmaf(dtrs[btl][r], wreg[r], a2);
                float sp = (a2 > 15.f) ? a2 : log1pf(__expf(a2));
                g_dtT[(size_t)hh * BT + bt0 + btl] = sp;
            }
            __syncthreads();
        }
    }
    grid_barrier();

    // ---- phase 4: selective scan -> g_yh/g_yl [bt][h] (256 tasks of 16 ch) ----
    {
        bf16 (*s_yh)[16] = (bf16(*)[16])(s_raw);
        bf16 (*s_yl)[16] = (bf16(*)[16])(s_raw + 1024);
        const int cid = tid >> 4;       // 0..15
        const int n   = tid & 15;
        const int fl_t = tid >> 3;      // 0..31
        const int fl_h = (tid & 7) * 2; // 0..14
        for (int task = bid; task < (BB * HH) / 16; task += nbk) {
            const int b    = task >> 5;
            const int hblk = (task & 31) * 16;
            const int h    = hblk + cid;
            float Ap = Apw[h * NN + n];
            float A  = -__expf(Ap);
            float invA = (fabsf(A) < 1e-5f) ? 1.f : (1.f / A);
            float Dp = Dpw[h];
            const float* xrow = g_vcT + (size_t)h * BT + b * TT;
            const float* drow = g_dtT + (size_t)h * BT + b * TT;
            float state = 0.f;
            for (int tb = 0; tb < TT; tb += 32) {
                #pragma unroll 8
                for (int tt = 0; tt < 32; tt++) {
                    int t = tb + tt;
                    float dtv = drow[t];
                    float x   = xrow[t];
                    float discA = __expf(A * dtv);
                    float discB = (discA - 1.f) * invA * dtv;
                    state = fmaf(discA, state, discB * x);
                    float part = state * Ap;
                    part += __shfl_xor_sync(0xffffffffu, part, 8);
                    part += __shfl_xor_sync(0xffffffffu, part, 4);
                    part += __shfl_xor_sync(0xffffffffu, part, 2);
                    part += __shfl_xor_sync(0xffffffffu, part, 1);
                    if (n == 0) {
                        float y = fmaf(Dp, x, part);
                        bf16 hh_, ll_;
                        split_bf16(y, hh_, ll_);
                        s_yh[tt][cid] = hh_;
                        s_yl[tt][cid] = ll_;
                    }
                }
                __syncthreads();
                size_t base = (size_t)(b * TT + tb + fl_t) * HH + hblk + fl_h;
                *(unsigned int*)(g_yh + base) = *(unsigned int*)&s_yh[fl_t][fl_h];
                *(unsigned int*)(g_yl + base) = *(unsigned int*)&s_yl[fl_t][fl_h];
                __syncthreads();
            }
        }
    }
    grid_barrier();

    // ---- phase 5: gemm2  h[bt][d] += y @ out_w^T (256 tiles: 64 m x 4 n) ----
    for (int t = bid; t < 256; t += nbk)
        gemm_tile(s_raw, g_yh, g_yl, owh, owl, g_h, DD, HH, 1,
                  (t >> 2) * 128, (t & 3) * 64);
}

// ---------------- final LN (last token) + head1(silu) + head2 ----------------
__global__ void final_kernel(const float* __restrict__ fg,
                             const float* __restrict__ fb,
                             const float* __restrict__ w1,
                             const float* __restrict__ b1,
                             const float* __restrict__ w2,
                             const float* __restrict__ b2,
                             float* __restrict__ out) {
    int b = blockIdx.x;
    int tid = threadIdx.x;
    __shared__ float red1[8], red2[8];
    __shared__ float s_ln[DD];
    __shared__ float s_h1[DD];
    const float* row = g_h + (size_t)(b * TT + (TT - 1)) * DD;
    float v = row[tid];
    float s = v;
    #pragma unroll
    for (int o = 16; o; o >>= 1) s += __shfl_xor_sync(0xffffffffu, s, o);
    if ((tid & 31) == 0) red1[tid >> 5] = s;
    __syncthreads();
    float mean = 0.f;
    #pragma unroll
    for (int i = 0; i < 8; i++) mean += red1[i];
    mean *= (1.f / 256.f);
    float c = v - mean;
    float cc = c * c;
    #pragma unroll
    for (int o = 16; o; o >>= 1) cc += __shfl_xor_sync(0xffffffffu, cc, o);
    if ((tid & 31) == 0) red2[tid >> 5] = cc;
    __syncthreads();
    float var = 0.f;
    #pragma unroll
    for (int i = 0; i < 8; i++) var += red2[i];
    var *= (1.f / 256.f);
    s_ln[tid] = c * rsqrtf(var + 1e-5f) * fg[tid] + fb[tid];
    __syncthreads();
    float acc = b1[tid];
    const float* w1r = w1 + tid * DD;
    #pragma unroll 8
    for (int k = 0; k < DD; k++) acc = fmaf(s_ln[k], w1r[k], acc);
    s_h1[tid] = silu_f(acc);
    __syncthreads();
    if (tid < 96) {
        float a2 = b2[tid];
        const float* w2r = w2 + tid * DD;
        #pragma unroll 8
        for (int k = 0; k < DD; k++) a2 = fmaf(s_h1[k], w2r[k], a2);
        out[b * 96 + tid] = a2;
    }
}

// ---------------- launcher: 6 graph nodes total ----------------
extern "C" void kernel_launch(void* const* d_in, const int* in_sizes, int n_in,
                              void* d_out, int out_size) {
    const float* x      = (const float*)d_in[0];
    const float* emb_w  = (const float*)d_in[1];
    const float* emb_b  = (const float*)d_in[2];
    const float* norm_g = (const float*)d_in[3];
    const float* norm_b = (const float*)d_in[4];
    const float* in_w   = (const float*)d_in[5];
    const float* conv_w = (const float*)d_in[6];
    const float* A_p    = (const float*)d_in[7];
    const float* D_p    = (const float*)d_in[8];
    const float* dt1_w  = (const float*)d_in[9];
    const float* dt1_b  = (const float*)d_in[10];
    const float* dt2_w  = (const float*)d_in[11];
    const float* dt2_b  = (const float*)d_in[12];
    const float* out_w  = (const float*)d_in[13];
    const float* fin_g  = (const float*)d_in[14];
    const float* fin_b  = (const float*)d_in[15];
    const float* h1_w   = (const float*)d_in[16];
    const float* h1_b   = (const float*)d_in[17];
    const float* h2_w   = (const float*)d_in[18];
    const float* h2_b   = (const float*)d_in[19];
    float* out = (float*)d_out;

    bf16 *piwh, *piwl, *powh, *powl;
    cudaGetSymbolAddress((void**)&piwh, g_iwh);
    cudaGetSymbolAddress((void**)&piwl, g_iwl);
    cudaGetSymbolAddress((void**)&powh, g_owh);
    cudaGetSymbolAddress((void**)&powl, g_owl);

    emb_split_kernel<<<BT + (2 * NW) / 256, 256>>>(x, emb_w, emb_b, in_w, out_w);

    for (int l = 0; l < LL; l++) {
        layer_kernel<<<GRID_PERSIST, 256>>>(
            norm_g + l * DD, norm_b + l * DD,
            conv_w + (size_t)l * HH * 3,
            A_p + (size_t)l * HH * NN, D_p + l * HH,
            dt1_w + (size_t)l * RR * HH, dt1_b + l * RR,
            dt2_w + (size_t)l * HH * RR, dt2_b + l * HH,
            piwh + (size_t)l * HH * DD, piwl + (size_t)l * HH * DD,
            powh + (size_t)l * DD * HH, powl + (size_t)l * DD * HH);
    }

    final_kernel<<<BB, 256>>>(fin_g, fin_b, h1_w, h1_b, h2_w, h2_b, out);
}